// round 1
// baseline (speedup 1.0000x reference)
#include <cuda_runtime.h>
#include <math.h>

#define NN 50000
#define NE 800000
#define D  128
#define DO 64
#define NC 40
#define AP 68   // padded node-stride for transposed smem tiles (bank-spread, 16B-aligned)

// Scratch (device globals: no allocation allowed)
__device__ float g_agg[(size_t)NN * D];
__device__ float g_x1[(size_t)NN * D];
__device__ float g_x2[(size_t)NN * D];
__device__ float g_p[(size_t)NN * DO];
__device__ float g_agg64[(size_t)NN * DO];
__device__ float g_cnt[NN];

__device__ __forceinline__ float gelu_exact(float v) {
    return 0.5f * v * (1.0f + erff(v * 0.70710678118654752f));
}

// ---------------- zero / count ----------------

__global__ void zero_agg128_cnt() {
    int i = blockIdx.x * blockDim.x + threadIdx.x;
    if (i < NN * 32) ((float4*)g_agg)[i] = make_float4(0.f, 0.f, 0.f, 0.f);
    if (i < NN) g_cnt[i] = 0.f;
}
__global__ void zero_agg128() {
    int i = blockIdx.x * blockDim.x + threadIdx.x;
    if (i < NN * 32) ((float4*)g_agg)[i] = make_float4(0.f, 0.f, 0.f, 0.f);
}
__global__ void zero_agg64() {
    int i = blockIdx.x * blockDim.x + threadIdx.x;
    if (i < NN * 16) ((float4*)g_agg64)[i] = make_float4(0.f, 0.f, 0.f, 0.f);
}

__global__ void count_edges(const int* __restrict__ dst) {
    int e = blockIdx.x * blockDim.x + threadIdx.x;
    if (e < NE) atomicAdd(&g_cnt[dst[e]], 1.0f);
}

// ---------------- scatter (sum over edges) ----------------
// One warp per edge: 32 lanes x float4 = 128 floats. Gather is L2-resident
// (x fits in L2); atomics land as RED.E.ADD.F32 spread over 25.6MB.

__global__ void scatter128(const float* __restrict__ x,
                           const int* __restrict__ src,
                           const int* __restrict__ dst) {
    int t = blockIdx.x * blockDim.x + threadIdx.x;
    if (t >= NE * 32) return;
    int e = t >> 5, q = t & 31;
    int s = __ldg(&src[e]);
    int d = __ldg(&dst[e]);
    float4 v = __ldg(&((const float4*)x)[(size_t)s * 32 + q]);
    float* a = &g_agg[(size_t)d * 128 + q * 4];
    atomicAdd(a + 0, v.x); atomicAdd(a + 1, v.y);
    atomicAdd(a + 2, v.z); atomicAdd(a + 3, v.w);
}

// 64-dim scatter of p = x2 @ Wl3 (GEMM pushed before aggregation: linearity)
__global__ void scatter64(const int* __restrict__ src,
                          const int* __restrict__ dst) {
    int t = blockIdx.x * blockDim.x + threadIdx.x;
    if (t >= NE * 16) return;
    int e = t >> 4, q = t & 15;
    int s = __ldg(&src[e]);
    int d = __ldg(&dst[e]);
    float4 v = __ldg(&((const float4*)g_p)[(size_t)s * 16 + q]);
    float* a = &g_agg64[(size_t)d * 64 + q * 4];
    atomicAdd(a + 0, v.x); atomicAdd(a + 1, v.y);
    atomicAdd(a + 2, v.z); atomicAdd(a + 3, v.w);
}

// ---------------- fused SAGE block: (agg/cnt)@Wl + bl + x@Wr -> LN -> GELU -> +x ----
// 64-node tile per block, 256 threads. Full Wl,Wr in smem (128KB) + transposed
// A tiles (agg scaled by 1/cnt, and x). Microtile: warp -> 8 nodes, lane -> 4 cols.
// Per k: 6 x LDS.128 (4 broadcast), 64 FFMA. Epilogue: warp-shuffle LN + erff GELU + residual.

__global__ __launch_bounds__(256) void sage_block(
    const float* __restrict__ xin,
    const float* __restrict__ Wl, const float* __restrict__ bl,
    const float* __restrict__ Wr,
    const float* __restrict__ gma, const float* __restrict__ bta,
    float* __restrict__ xout)
{
    extern __shared__ float sm[];
    float* Wsl = sm;                 // [128][128]
    float* Wsr = Wsl + D * D;        // [128][128]
    float* Aa  = Wsr + D * D;        // [128][AP] transposed (agg * inv_cnt)
    float* Ax  = Aa + D * AP;        // [128][AP] transposed (x)
    const int tid = threadIdx.x;
    const int node0 = blockIdx.x * 64;

    for (int i = tid; i < D * D / 4; i += 256) {
        ((float4*)Wsl)[i] = __ldg(&((const float4*)Wl)[i]);
        ((float4*)Wsr)[i] = __ldg(&((const float4*)Wr)[i]);
    }
    {
        int q = tid & 31, nl = tid >> 5;
        for (int nn = nl; nn < 64; nn += 8) {
            int gn = node0 + nn;
            float4 av = make_float4(0.f, 0.f, 0.f, 0.f), xv = av;
            float ic = 0.f;
            if (gn < NN) {
                ic = 1.0f / fmaxf(g_cnt[gn], 1.0f);
                av = __ldg(&((const float4*)g_agg)[(size_t)gn * 32 + q]);
                xv = __ldg(&((const float4*)xin)[(size_t)gn * 32 + q]);
            }
            int k = q * 4;
            Aa[(k + 0) * AP + nn] = av.x * ic; Aa[(k + 1) * AP + nn] = av.y * ic;
            Aa[(k + 2) * AP + nn] = av.z * ic; Aa[(k + 3) * AP + nn] = av.w * ic;
            Ax[(k + 0) * AP + nn] = xv.x; Ax[(k + 1) * AP + nn] = xv.y;
            Ax[(k + 2) * AP + nn] = xv.z; Ax[(k + 3) * AP + nn] = xv.w;
        }
    }
    __syncthreads();

    const int warp = tid >> 5, lane = tid & 31;
    const int nbase = warp * 8, cbase = lane * 4;
    float acc[8][4];
    #pragma unroll
    for (int i = 0; i < 8; i++) { acc[i][0] = 0.f; acc[i][1] = 0.f; acc[i][2] = 0.f; acc[i][3] = 0.f; }

    #pragma unroll 4
    for (int k = 0; k < D; k++) {
        float4 a0 = *(const float4*)&Aa[k * AP + nbase];
        float4 a1 = *(const float4*)&Aa[k * AP + nbase + 4];
        float4 x0 = *(const float4*)&Ax[k * AP + nbase];
        float4 x1 = *(const float4*)&Ax[k * AP + nbase + 4];
        float4 wl = *(const float4*)&Wsl[k * D + cbase];
        float4 wr = *(const float4*)&Wsr[k * D + cbase];
        float a[8]  = {a0.x, a0.y, a0.z, a0.w, a1.x, a1.y, a1.z, a1.w};
        float xx[8] = {x0.x, x0.y, x0.z, x0.w, x1.x, x1.y, x1.z, x1.w};
        float wlv[4] = {wl.x, wl.y, wl.z, wl.w};
        float wrv[4] = {wr.x, wr.y, wr.z, wr.w};
        #pragma unroll
        for (int i = 0; i < 8; i++)
            #pragma unroll
            for (int j = 0; j < 4; j++)
                acc[i][j] += a[i] * wlv[j] + xx[i] * wrv[j];
    }

    float4 blv = __ldg(&((const float4*)bl)[lane]);
    float4 gv  = __ldg(&((const float4*)gma)[lane]);
    float4 bv  = __ldg(&((const float4*)bta)[lane]);
    float gvv[4] = {gv.x, gv.y, gv.z, gv.w};
    float bvv[4] = {bv.x, bv.y, bv.z, bv.w};
    float blvv[4] = {blv.x, blv.y, blv.z, blv.w};

    #pragma unroll
    for (int n = 0; n < 8; n++) {
        int gn = node0 + nbase + n;
        float h[4];
        #pragma unroll
        for (int j = 0; j < 4; j++) h[j] = acc[n][j] + blvv[j];
        float s1 = h[0] + h[1] + h[2] + h[3];
        float s2 = h[0]*h[0] + h[1]*h[1] + h[2]*h[2] + h[3]*h[3];
        #pragma unroll
        for (int off = 16; off; off >>= 1) {
            s1 += __shfl_xor_sync(0xffffffffu, s1, off);
            s2 += __shfl_xor_sync(0xffffffffu, s2, off);
        }
        float mu = s1 * (1.0f / 128.0f);
        float var = s2 * (1.0f / 128.0f) - mu * mu;
        float rstd = rsqrtf(var + 1e-5f);
        float o[4];
        #pragma unroll
        for (int j = 0; j < 4; j++) {
            float y = (h[j] - mu) * rstd * gvv[j] + bvv[j];
            float r = Ax[(cbase + j) * AP + nbase + n];
            o[j] = gelu_exact(y) + r;
        }
        if (gn < NN)
            ((float4*)xout)[(size_t)gn * 32 + lane] = make_float4(o[0], o[1], o[2], o[3]);
    }
}

// ---------------- p = x2 @ Wl3  (N x 128 @ 128 x 64) ----------------

__global__ __launch_bounds__(256) void gemm_p_kernel(const float* __restrict__ Wl3)
{
    extern __shared__ float sm[];
    float* Ws = sm;              // [128][64]
    float* Ax = Ws + D * DO;     // [128][AP]
    const int tid = threadIdx.x;
    const int node0 = blockIdx.x * 64;

    for (int i = tid; i < D * DO / 4; i += 256)
        ((float4*)Ws)[i] = __ldg(&((const float4*)Wl3)[i]);
    {
        int q = tid & 31, nl = tid >> 5;
        for (int nn = nl; nn < 64; nn += 8) {
            int gn = node0 + nn;
            float4 xv = make_float4(0.f, 0.f, 0.f, 0.f);
            if (gn < NN) xv = __ldg(&((const float4*)g_x2)[(size_t)gn * 32 + q]);
            int k = q * 4;
            Ax[(k + 0) * AP + nn] = xv.x; Ax[(k + 1) * AP + nn] = xv.y;
            Ax[(k + 2) * AP + nn] = xv.z; Ax[(k + 3) * AP + nn] = xv.w;
        }
    }
    __syncthreads();

    const int warp = tid >> 5, lane = tid & 31;
    const int nbase = warp * 8, c2 = lane * 2;
    float acc[8][2];
    #pragma unroll
    for (int i = 0; i < 8; i++) { acc[i][0] = 0.f; acc[i][1] = 0.f; }

    #pragma unroll 4
    for (int k = 0; k < D; k++) {
        float4 a0 = *(const float4*)&Ax[k * AP + nbase];
        float4 a1 = *(const float4*)&Ax[k * AP + nbase + 4];
        float2 w  = *(const float2*)&Ws[k * DO + c2];
        float a[8] = {a0.x, a0.y, a0.z, a0.w, a1.x, a1.y, a1.z, a1.w};
        #pragma unroll
        for (int i = 0; i < 8; i++) {
            acc[i][0] += a[i] * w.x;
            acc[i][1] += a[i] * w.y;
        }
    }
    #pragma unroll
    for (int n = 0; n < 8; n++) {
        int gn = node0 + nbase + n;
        if (gn < NN)
            ((float2*)g_p)[(size_t)gn * 32 + lane] = make_float2(acc[n][0], acc[n][1]);
    }
}

// -------- layer3 epilogue + classifier: gelu(agg_p/cnt + bl3 + x2@Wr3) -> LN -> @Wc + bcls ----

__global__ __launch_bounds__(64) void out_kernel(
    const float* __restrict__ Wr3, const float* __restrict__ bl3,
    const float* __restrict__ gc, const float* __restrict__ bc,
    const float* __restrict__ Wc, const float* __restrict__ bcls,
    float* __restrict__ out)
{
    __shared__ float sx[128];
    __shared__ float sv[64];
    __shared__ float red[4];
    const int n = blockIdx.x, t = threadIdx.x;

    ((float2*)sx)[t] = ((const float2*)g_x2)[(size_t)n * 64 + t];
    __syncthreads();

    float ic = 1.0f / fmaxf(g_cnt[n], 1.0f);
    float acc = __ldg(&bl3[t]) + g_agg64[(size_t)n * 64 + t] * ic;
    #pragma unroll 8
    for (int k = 0; k < D; k++)
        acc += sx[k] * __ldg(&Wr3[k * DO + t]);

    float u = gelu_exact(acc);
    float s1 = u, s2 = u * u;
    #pragma unroll
    for (int off = 16; off; off >>= 1) {
        s1 += __shfl_xor_sync(0xffffffffu, s1, off);
        s2 += __shfl_xor_sync(0xffffffffu, s2, off);
    }
    int lane = t & 31, w = t >> 5;
    if (lane == 0) { red[w] = s1; red[2 + w] = s2; }
    __syncthreads();
    float S1 = red[0] + red[1], S2 = red[2] + red[3];
    float mu = S1 * (1.0f / 64.0f);
    float var = S2 * (1.0f / 64.0f) - mu * mu;
    float rstd = rsqrtf(var + 1e-5f);
    float v = (u - mu) * rstd * __ldg(&gc[t]) + __ldg(&bc[t]);
    sv[t] = v;
    __syncthreads();

    if (t < NC) {
        float o = __ldg(&bcls[t]);
        #pragma unroll
        for (int dd = 0; dd < DO; dd++)
            o += sv[dd] * __ldg(&Wc[dd * NC + t]);
        out[(size_t)n * NC + t] = o;
    }
}

// ---------------- launcher ----------------

extern "C" void kernel_launch(void* const* d_in, const int* in_sizes, int n_in,
                              void* d_out, int out_size)
{
    const float* x    = (const float*)d_in[0];
    const int*   ei   = (const int*)d_in[1];
    const float* Wl1  = (const float*)d_in[2];
    const float* bl1  = (const float*)d_in[3];
    const float* Wr1  = (const float*)d_in[4];
    const float* g1   = (const float*)d_in[5];
    const float* b1   = (const float*)d_in[6];
    const float* Wl2  = (const float*)d_in[7];
    const float* bl2  = (const float*)d_in[8];
    const float* Wr2  = (const float*)d_in[9];
    const float* g2   = (const float*)d_in[10];
    const float* b2   = (const float*)d_in[11];
    const float* Wl3  = (const float*)d_in[12];
    const float* bl3  = (const float*)d_in[13];
    const float* Wr3  = (const float*)d_in[14];
    const float* gc   = (const float*)d_in[15];
    const float* bc   = (const float*)d_in[16];
    const float* Wc   = (const float*)d_in[17];
    const float* bcls = (const float*)d_in[18];
    const int* src = ei;
    const int* dst = ei + NE;
    float* out = (float*)d_out;

    void *p_x1 = nullptr, *p_x2 = nullptr;
    cudaGetSymbolAddress(&p_x1, g_x1);
    cudaGetSymbolAddress(&p_x2, g_x2);

    const size_t smem_fused = (size_t)(2 * D * D + 2 * D * AP) * sizeof(float); // 200704 B
    const size_t smem_p     = (size_t)(D * DO + D * AP) * sizeof(float);        // 67584 B
    cudaFuncSetAttribute(sage_block, cudaFuncAttributeMaxDynamicSharedMemorySize, (int)smem_fused);
    cudaFuncSetAttribute(gemm_p_kernel, cudaFuncAttributeMaxDynamicSharedMemorySize, (int)smem_p);

    const int nbz = (NN * 32 + 255) / 256;
    const int nbn = (NN + 63) / 64;

    // Layer 1
    zero_agg128_cnt<<<nbz, 256>>>();
    count_edges<<<(NE + 255) / 256, 256>>>(dst);
    scatter128<<<(NE * 32) / 256, 256>>>(x, src, dst);
    sage_block<<<nbn, 256, smem_fused>>>(x, Wl1, bl1, Wr1, g1, b1, (float*)p_x1);

    // Layer 2
    zero_agg128<<<nbz, 256>>>();
    scatter128<<<(NE * 32) / 256, 256>>>((const float*)p_x1, src, dst);
    sage_block<<<nbn, 256, smem_fused>>>((const float*)p_x1, Wl2, bl2, Wr2, g2, b2, (float*)p_x2);

    // Layer 3: GEMM before scatter (64-dim messages), then fused epilogue + classifier
    gemm_p_kernel<<<nbn, 256, smem_p>>>(Wl3);
    zero_agg64<<<(NN * 16 + 255) / 256, 256>>>();
    scatter64<<<(NE * 16) / 256, 256>>>(src, dst);
    out_kernel<<<NN, 64>>>(Wr3, bl3, gc, bc, Wc, bcls, out);
}

// round 2
// speedup vs baseline: 1.7905x; 1.7905x over previous
#include <cuda_runtime.h>
#include <math.h>

#define NN 50000
#define NE 800000
#define D  128
#define DO 64
#define NC 40
#define AP 68        // padded node-stride for transposed smem tiles
#define SCAN_T 512
#define SCAN_B ((NN + SCAN_T - 1) / SCAN_T)   // 98

// Scratch (device globals: no allocation allowed)
__device__ float g_agg[(size_t)NN * D];
__device__ float g_x1[(size_t)NN * D];
__device__ float g_x2[(size_t)NN * D];
__device__ float g_p[(size_t)NN * DO];
__device__ float g_agg64[(size_t)NN * DO];
__device__ int   g_deg[NN];
__device__ int   g_off[NN];
__device__ int   g_cur[NN];
__device__ int   g_bsum[SCAN_B];
__device__ int   g_esrc[NE];

__device__ __forceinline__ float gelu_exact(float v) {
    return 0.5f * v * (1.0f + erff(v * 0.70710678118654752f));
}

// ---------------- CSR build ----------------

__global__ void zero_deg_cur() {
    int i = blockIdx.x * blockDim.x + threadIdx.x;
    if (i < NN) { g_deg[i] = 0; g_cur[i] = 0; }
}

__global__ void count_deg(const int* __restrict__ dst) {
    int e = blockIdx.x * blockDim.x + threadIdx.x;
    if (e < NE) atomicAdd(&g_deg[dst[e]], 1);
}

__global__ void scan_local() {
    __shared__ int s[SCAN_T];
    int t = threadIdx.x;
    int i = blockIdx.x * SCAN_T + t;
    int v = (i < NN) ? g_deg[i] : 0;
    s[t] = v;
    __syncthreads();
    #pragma unroll
    for (int off = 1; off < SCAN_T; off <<= 1) {
        int a = (t >= off) ? s[t - off] : 0;
        __syncthreads();
        s[t] += a;
        __syncthreads();
    }
    if (i < NN) g_off[i] = s[t] - v;              // exclusive within block
    if (t == SCAN_T - 1) g_bsum[blockIdx.x] = s[t];
}

__global__ void scan_bsum() {
    __shared__ int s[128];
    int t = threadIdx.x;
    int v = (t < SCAN_B) ? g_bsum[t] : 0;
    s[t] = v;
    __syncthreads();
    #pragma unroll
    for (int off = 1; off < 128; off <<= 1) {
        int a = (t >= off) ? s[t - off] : 0;
        __syncthreads();
        s[t] += a;
        __syncthreads();
    }
    if (t < SCAN_B) g_bsum[t] = s[t] - v;         // exclusive
}

__global__ void scan_add() {
    int i = blockIdx.x * blockDim.x + threadIdx.x;
    if (i < NN) g_off[i] += g_bsum[i / SCAN_T];
}

__global__ void fill_edges(const int* __restrict__ src, const int* __restrict__ dst) {
    int e = blockIdx.x * blockDim.x + threadIdx.x;
    if (e >= NE) return;
    int d = dst[e];
    int pos = g_off[d] + atomicAdd(&g_cur[d], 1);
    g_esrc[pos] = src[e];
}

// ---------------- gather mean-aggregation (no atomics) ----------------
// One warp per node. Edge indices loaded coalesced, distributed by shfl.
// Each lane accumulates a float4 slice (128 floats / 32 lanes). Output pre-normalized.

__global__ __launch_bounds__(256) void gather128(const float* __restrict__ x) {
    int gw = (blockIdx.x * blockDim.x + threadIdx.x) >> 5;
    int lane = threadIdx.x & 31;
    if (gw >= NN) return;
    int start = g_off[gw], deg = g_deg[gw];
    float4 acc = make_float4(0.f, 0.f, 0.f, 0.f);
    for (int base = 0; base < deg; base += 32) {
        int lim = min(32, deg - base);
        int idx = (lane < lim) ? __ldg(&g_esrc[start + base + lane]) : 0;
        for (int j = 0; j < lim; j++) {
            int s = __shfl_sync(0xffffffffu, idx, j);
            float4 v = __ldg(&((const float4*)x)[(size_t)s * 32 + lane]);
            acc.x += v.x; acc.y += v.y; acc.z += v.z; acc.w += v.w;
        }
    }
    float inv = 1.0f / fmaxf((float)deg, 1.0f);
    ((float4*)g_agg)[(size_t)gw * 32 + lane] =
        make_float4(acc.x * inv, acc.y * inv, acc.z * inv, acc.w * inv);
}

__global__ __launch_bounds__(256) void gather64() {
    int gw = (blockIdx.x * blockDim.x + threadIdx.x) >> 5;
    int lane = threadIdx.x & 31;
    if (gw >= NN) return;
    int start = g_off[gw], deg = g_deg[gw];
    float2 acc = make_float2(0.f, 0.f);
    for (int base = 0; base < deg; base += 32) {
        int lim = min(32, deg - base);
        int idx = (lane < lim) ? __ldg(&g_esrc[start + base + lane]) : 0;
        for (int j = 0; j < lim; j++) {
            int s = __shfl_sync(0xffffffffu, idx, j);
            float2 v = __ldg(&((const float2*)g_p)[(size_t)s * 32 + lane]);
            acc.x += v.x; acc.y += v.y;
        }
    }
    float inv = 1.0f / fmaxf((float)deg, 1.0f);
    ((float2*)g_agg64)[(size_t)gw * 32 + lane] = make_float2(acc.x * inv, acc.y * inv);
}

// ---------------- fused SAGE block: agg@Wl + bl + x@Wr -> LN -> GELU -> +x ----

__global__ __launch_bounds__(256) void sage_block(
    const float* __restrict__ xin,
    const float* __restrict__ Wl, const float* __restrict__ bl,
    const float* __restrict__ Wr,
    const float* __restrict__ gma, const float* __restrict__ bta,
    float* __restrict__ xout)
{
    extern __shared__ float sm[];
    float* Wsl = sm;                 // [128][128]
    float* Wsr = Wsl + D * D;        // [128][128]
    float* Aa  = Wsr + D * D;        // [128][AP] transposed (agg, pre-normalized)
    float* Ax  = Aa + D * AP;        // [128][AP] transposed (x)
    const int tid = threadIdx.x;
    const int node0 = blockIdx.x * 64;

    for (int i = tid; i < D * D / 4; i += 256) {
        ((float4*)Wsl)[i] = __ldg(&((const float4*)Wl)[i]);
        ((float4*)Wsr)[i] = __ldg(&((const float4*)Wr)[i]);
    }
    {
        int q = tid & 31, nl = tid >> 5;
        for (int nn = nl; nn < 64; nn += 8) {
            int gn = node0 + nn;
            float4 av = make_float4(0.f, 0.f, 0.f, 0.f), xv = av;
            if (gn < NN) {
                av = __ldg(&((const float4*)g_agg)[(size_t)gn * 32 + q]);
                xv = __ldg(&((const float4*)xin)[(size_t)gn * 32 + q]);
            }
            int k = q * 4;
            Aa[(k + 0) * AP + nn] = av.x; Aa[(k + 1) * AP + nn] = av.y;
            Aa[(k + 2) * AP + nn] = av.z; Aa[(k + 3) * AP + nn] = av.w;
            Ax[(k + 0) * AP + nn] = xv.x; Ax[(k + 1) * AP + nn] = xv.y;
            Ax[(k + 2) * AP + nn] = xv.z; Ax[(k + 3) * AP + nn] = xv.w;
        }
    }
    __syncthreads();

    const int warp = tid >> 5, lane = tid & 31;
    const int nbase = warp * 8, cbase = lane * 4;
    float acc[8][4];
    #pragma unroll
    for (int i = 0; i < 8; i++) { acc[i][0] = 0.f; acc[i][1] = 0.f; acc[i][2] = 0.f; acc[i][3] = 0.f; }

    #pragma unroll 4
    for (int k = 0; k < D; k++) {
        float4 a0 = *(const float4*)&Aa[k * AP + nbase];
        float4 a1 = *(const float4*)&Aa[k * AP + nbase + 4];
        float4 x0 = *(const float4*)&Ax[k * AP + nbase];
        float4 x1 = *(const float4*)&Ax[k * AP + nbase + 4];
        float4 wl = *(const float4*)&Wsl[k * D + cbase];
        float4 wr = *(const float4*)&Wsr[k * D + cbase];
        float a[8]  = {a0.x, a0.y, a0.z, a0.w, a1.x, a1.y, a1.z, a1.w};
        float xx[8] = {x0.x, x0.y, x0.z, x0.w, x1.x, x1.y, x1.z, x1.w};
        float wlv[4] = {wl.x, wl.y, wl.z, wl.w};
        float wrv[4] = {wr.x, wr.y, wr.z, wr.w};
        #pragma unroll
        for (int i = 0; i < 8; i++)
            #pragma unroll
            for (int j = 0; j < 4; j++)
                acc[i][j] += a[i] * wlv[j] + xx[i] * wrv[j];
    }

    float4 blv = __ldg(&((const float4*)bl)[lane]);
    float4 gv  = __ldg(&((const float4*)gma)[lane]);
    float4 bv  = __ldg(&((const float4*)bta)[lane]);
    float gvv[4] = {gv.x, gv.y, gv.z, gv.w};
    float bvv[4] = {bv.x, bv.y, bv.z, bv.w};
    float blvv[4] = {blv.x, blv.y, blv.z, blv.w};

    #pragma unroll
    for (int n = 0; n < 8; n++) {
        int gn = node0 + nbase + n;
        float h[4];
        #pragma unroll
        for (int j = 0; j < 4; j++) h[j] = acc[n][j] + blvv[j];
        float s1 = h[0] + h[1] + h[2] + h[3];
        float s2 = h[0]*h[0] + h[1]*h[1] + h[2]*h[2] + h[3]*h[3];
        #pragma unroll
        for (int off = 16; off; off >>= 1) {
            s1 += __shfl_xor_sync(0xffffffffu, s1, off);
            s2 += __shfl_xor_sync(0xffffffffu, s2, off);
        }
        float mu = s1 * (1.0f / 128.0f);
        float var = s2 * (1.0f / 128.0f) - mu * mu;
        float rstd = rsqrtf(var + 1e-5f);
        float o[4];
        #pragma unroll
        for (int j = 0; j < 4; j++) {
            float y = (h[j] - mu) * rstd * gvv[j] + bvv[j];
            float r = Ax[(cbase + j) * AP + nbase + n];
            o[j] = gelu_exact(y) + r;
        }
        if (gn < NN)
            ((float4*)xout)[(size_t)gn * 32 + lane] = make_float4(o[0], o[1], o[2], o[3]);
    }
}

// ---------------- p = x2 @ Wl3  (N x 128 @ 128 x 64) ----------------

__global__ __launch_bounds__(256) void gemm_p_kernel(const float* __restrict__ Wl3)
{
    extern __shared__ float sm[];
    float* Ws = sm;              // [128][64]
    float* Ax = Ws + D * DO;     // [128][AP]
    const int tid = threadIdx.x;
    const int node0 = blockIdx.x * 64;

    for (int i = tid; i < D * DO / 4; i += 256)
        ((float4*)Ws)[i] = __ldg(&((const float4*)Wl3)[i]);
    {
        int q = tid & 31, nl = tid >> 5;
        for (int nn = nl; nn < 64; nn += 8) {
            int gn = node0 + nn;
            float4 xv = make_float4(0.f, 0.f, 0.f, 0.f);
            if (gn < NN) xv = __ldg(&((const float4*)g_x2)[(size_t)gn * 32 + q]);
            int k = q * 4;
            Ax[(k + 0) * AP + nn] = xv.x; Ax[(k + 1) * AP + nn] = xv.y;
            Ax[(k + 2) * AP + nn] = xv.z; Ax[(k + 3) * AP + nn] = xv.w;
        }
    }
    __syncthreads();

    const int warp = tid >> 5, lane = tid & 31;
    const int nbase = warp * 8, c2 = lane * 2;
    float acc[8][2];
    #pragma unroll
    for (int i = 0; i < 8; i++) { acc[i][0] = 0.f; acc[i][1] = 0.f; }

    #pragma unroll 4
    for (int k = 0; k < D; k++) {
        float4 a0 = *(const float4*)&Ax[k * AP + nbase];
        float4 a1 = *(const float4*)&Ax[k * AP + nbase + 4];
        float2 w  = *(const float2*)&Ws[k * DO + c2];
        float a[8] = {a0.x, a0.y, a0.z, a0.w, a1.x, a1.y, a1.z, a1.w};
        #pragma unroll
        for (int i = 0; i < 8; i++) {
            acc[i][0] += a[i] * w.x;
            acc[i][1] += a[i] * w.y;
        }
    }
    #pragma unroll
    for (int n = 0; n < 8; n++) {
        int gn = node0 + nbase + n;
        if (gn < NN)
            ((float2*)g_p)[(size_t)gn * 32 + lane] = make_float2(acc[n][0], acc[n][1]);
    }
}

// -------- layer3 epilogue + classifier ----------------

__global__ __launch_bounds__(64) void out_kernel(
    const float* __restrict__ Wr3, const float* __restrict__ bl3,
    const float* __restrict__ gc, const float* __restrict__ bc,
    const float* __restrict__ Wc, const float* __restrict__ bcls,
    float* __restrict__ out)
{
    __shared__ float sx[128];
    __shared__ float sv[64];
    __shared__ float red[4];
    const int n = blockIdx.x, t = threadIdx.x;

    ((float2*)sx)[t] = ((const float2*)g_x2)[(size_t)n * 64 + t];
    __syncthreads();

    float acc = __ldg(&bl3[t]) + g_agg64[(size_t)n * 64 + t];
    #pragma unroll 8
    for (int k = 0; k < D; k++)
        acc += sx[k] * __ldg(&Wr3[k * DO + t]);

    float u = gelu_exact(acc);
    float s1 = u, s2 = u * u;
    #pragma unroll
    for (int off = 16; off; off >>= 1) {
        s1 += __shfl_xor_sync(0xffffffffu, s1, off);
        s2 += __shfl_xor_sync(0xffffffffu, s2, off);
    }
    int lane = t & 31, w = t >> 5;
    if (lane == 0) { red[w] = s1; red[2 + w] = s2; }
    __syncthreads();
    float S1 = red[0] + red[1], S2 = red[2] + red[3];
    float mu = S1 * (1.0f / 64.0f);
    float var = S2 * (1.0f / 64.0f) - mu * mu;
    float rstd = rsqrtf(var + 1e-5f);
    float v = (u - mu) * rstd * __ldg(&gc[t]) + __ldg(&bc[t]);
    sv[t] = v;
    __syncthreads();

    if (t < NC) {
        float o = __ldg(&bcls[t]);
        #pragma unroll
        for (int dd = 0; dd < DO; dd++)
            o += sv[dd] * __ldg(&Wc[dd * NC + t]);
        out[(size_t)n * NC + t] = o;
    }
}

// ---------------- launcher ----------------

extern "C" void kernel_launch(void* const* d_in, const int* in_sizes, int n_in,
                              void* d_out, int out_size)
{
    const float* x    = (const float*)d_in[0];
    const int*   ei   = (const int*)d_in[1];
    const float* Wl1  = (const float*)d_in[2];
    const float* bl1  = (const float*)d_in[3];
    const float* Wr1  = (const float*)d_in[4];
    const float* g1   = (const float*)d_in[5];
    const float* b1   = (const float*)d_in[6];
    const float* Wl2  = (const float*)d_in[7];
    const float* bl2  = (const float*)d_in[8];
    const float* Wr2  = (const float*)d_in[9];
    const float* g2   = (const float*)d_in[10];
    const float* b2   = (const float*)d_in[11];
    const float* Wl3  = (const float*)d_in[12];
    const float* bl3  = (const float*)d_in[13];
    const float* Wr3  = (const float*)d_in[14];
    const float* gc   = (const float*)d_in[15];
    const float* bc   = (const float*)d_in[16];
    const float* Wc   = (const float*)d_in[17];
    const float* bcls = (const float*)d_in[18];
    const int* src = ei;
    const int* dst = ei + NE;
    float* out = (float*)d_out;

    void *p_x1 = nullptr, *p_x2 = nullptr;
    cudaGetSymbolAddress(&p_x1, g_x1);
    cudaGetSymbolAddress(&p_x2, g_x2);

    const size_t smem_fused = (size_t)(2 * D * D + 2 * D * AP) * sizeof(float); // 200704 B
    const size_t smem_p     = (size_t)(D * DO + D * AP) * sizeof(float);        // 67584 B
    cudaFuncSetAttribute(sage_block, cudaFuncAttributeMaxDynamicSharedMemorySize, (int)smem_fused);
    cudaFuncSetAttribute(gemm_p_kernel, cudaFuncAttributeMaxDynamicSharedMemorySize, (int)smem_p);

    const int nbn = (NN + 63) / 64;
    const int nbe = (NE + 255) / 256;
    const int nbw = ((NN * 32) + 255) / 256;   // one warp per node

    // CSR build (per launch; deterministic work)
    zero_deg_cur<<<(NN + 255) / 256, 256>>>();
    count_deg<<<nbe, 256>>>(dst);
    scan_local<<<SCAN_B, SCAN_T>>>();
    scan_bsum<<<1, 128>>>();
    scan_add<<<(NN + 255) / 256, 256>>>();
    fill_edges<<<nbe, 256>>>(src, dst);

    // Layer 1
    gather128<<<nbw, 256>>>(x);
    sage_block<<<nbn, 256, smem_fused>>>(x, Wl1, bl1, Wr1, g1, b1, (float*)p_x1);

    // Layer 2
    gather128<<<nbw, 256>>>((const float*)p_x1);
    sage_block<<<nbn, 256, smem_fused>>>((const float*)p_x1, Wl2, bl2, Wr2, g2, b2, (float*)p_x2);

    // Layer 3: GEMM before scatter (64-dim messages), then fused epilogue + classifier
    gemm_p_kernel<<<nbn, 256, smem_p>>>(Wl3);
    gather64<<<nbw, 256>>>();
    out_kernel<<<NN, 64>>>(Wr3, bl3, gc, bc, Wc, bcls, out);
}

// round 4
// speedup vs baseline: 2.5110x; 1.4024x over previous
#include <cuda_runtime.h>
#include <math.h>

#define NN 50000
#define NE 800000
#define D  128
#define DO 64
#define NC 40
#define AP 68        // padded node-stride for transposed smem tiles
#define AS 68        // padded stride for A chunks
#define KC 32        // k-chunk
#define SCAN_T 512
#define SCAN_B ((NN + SCAN_T - 1) / SCAN_T)   // 98

// Scratch (device globals: no allocation allowed)
__device__ float g_agg[(size_t)NN * D];
__device__ float g_x1[(size_t)NN * D];
__device__ float g_x2[(size_t)NN * D];
__device__ float g_p[(size_t)NN * DO];
__device__ float g_agg64[(size_t)NN * DO];
__device__ int   g_deg[NN];
__device__ int   g_off[NN];
__device__ int   g_cur[NN];
__device__ int   g_bsum[SCAN_B];
__device__ int   g_esrc[NE];

__device__ __forceinline__ float gelu_exact(float v) {
    return 0.5f * v * (1.0f + erff(v * 0.70710678118654752f));
}

// ---------------- CSR build ----------------

__global__ void zero_deg_cur() {
    int i = blockIdx.x * blockDim.x + threadIdx.x;
    if (i < NN) { g_deg[i] = 0; g_cur[i] = 0; }
}

__global__ void count_deg(const int* __restrict__ dst) {
    int e = blockIdx.x * blockDim.x + threadIdx.x;
    if (e < NE) atomicAdd(&g_deg[dst[e]], 1);
}

__global__ void scan_local() {
    __shared__ int s[SCAN_T];
    int t = threadIdx.x;
    int i = blockIdx.x * SCAN_T + t;
    int v = (i < NN) ? g_deg[i] : 0;
    s[t] = v;
    __syncthreads();
    #pragma unroll
    for (int off = 1; off < SCAN_T; off <<= 1) {
        int a = (t >= off) ? s[t - off] : 0;
        __syncthreads();
        s[t] += a;
        __syncthreads();
    }
    if (i < NN) g_off[i] = s[t] - v;
    if (t == SCAN_T - 1) g_bsum[blockIdx.x] = s[t];
}

__global__ void scan_bsum() {
    __shared__ int s[128];
    int t = threadIdx.x;
    int v = (t < SCAN_B) ? g_bsum[t] : 0;
    s[t] = v;
    __syncthreads();
    #pragma unroll
    for (int off = 1; off < 128; off <<= 1) {
        int a = (t >= off) ? s[t - off] : 0;
        __syncthreads();
        s[t] += a;
        __syncthreads();
    }
    if (t < SCAN_B) g_bsum[t] = s[t] - v;
}

__global__ void scan_add() {
    int i = blockIdx.x * blockDim.x + threadIdx.x;
    if (i < NN) g_off[i] += g_bsum[i / SCAN_T];
}

__global__ void fill_edges(const int* __restrict__ src, const int* __restrict__ dst) {
    int e = blockIdx.x * blockDim.x + threadIdx.x;
    if (e >= NE) return;
    int d = dst[e];
    int pos = g_off[d] + atomicAdd(&g_cur[d], 1);
    g_esrc[pos] = src[e];
}

// ---------------- gather mean-aggregation (no atomics) ----------------

__global__ __launch_bounds__(256) void gather128(const float* __restrict__ x) {
    int gw = (blockIdx.x * blockDim.x + threadIdx.x) >> 5;
    int lane = threadIdx.x & 31;
    if (gw >= NN) return;
    int start = g_off[gw], deg = g_deg[gw];
    float4 acc = make_float4(0.f, 0.f, 0.f, 0.f);
    for (int base = 0; base < deg; base += 32) {
        int lim = min(32, deg - base);
        int idx = (lane < lim) ? __ldg(&g_esrc[start + base + lane]) : 0;
        for (int j = 0; j < lim; j++) {
            int s = __shfl_sync(0xffffffffu, idx, j);
            float4 v = __ldg(&((const float4*)x)[(size_t)s * 32 + lane]);
            acc.x += v.x; acc.y += v.y; acc.z += v.z; acc.w += v.w;
        }
    }
    float inv = 1.0f / fmaxf((float)deg, 1.0f);
    ((float4*)g_agg)[(size_t)gw * 32 + lane] =
        make_float4(acc.x * inv, acc.y * inv, acc.z * inv, acc.w * inv);
}

__global__ __launch_bounds__(256) void gather64() {
    int gw = (blockIdx.x * blockDim.x + threadIdx.x) >> 5;
    int lane = threadIdx.x & 31;
    if (gw >= NN) return;
    int start = g_off[gw], deg = g_deg[gw];
    float2 acc = make_float2(0.f, 0.f);
    for (int base = 0; base < deg; base += 32) {
        int lim = min(32, deg - base);
        int idx = (lane < lim) ? __ldg(&g_esrc[start + base + lane]) : 0;
        for (int j = 0; j < lim; j++) {
            int s = __shfl_sync(0xffffffffu, idx, j);
            float2 v = __ldg(&((const float2*)g_p)[(size_t)s * 32 + lane]);
            acc.x += v.x; acc.y += v.y;
        }
    }
    float inv = 1.0f / fmaxf((float)deg, 1.0f);
    ((float2*)g_agg64)[(size_t)gw * 32 + lane] = make_float2(acc.x * inv, acc.y * inv);
}

// ---- fused SAGE block v2: K=256 concat GEMM, k-chunked, prefetch-pipelined ----
// h = [agg; x] @ [Wl; Wr] + bl -> LN -> GELU -> + x.
// 64-node x 128-col tile, K streamed in chunks of 32 through 25KB smem.
// 2 CTAs/SM (16 warps). Per k: 3 LDS.128 (2 broadcast), 32 FFMA per thread.

__global__ __launch_bounds__(256, 2) void sage_block2(
    const float* __restrict__ xin,
    const float* __restrict__ Wl, const float* __restrict__ bl,
    const float* __restrict__ Wr,
    const float* __restrict__ gma, const float* __restrict__ bta,
    float* __restrict__ xout)
{
    __shared__ float Ach[KC * AS];    // 8704 B  (transposed A chunk)
    __shared__ float Wch[KC * D];     // 16384 B (W chunk)
    const int tid = threadIdx.x;
    const int node0 = blockIdx.x * 64;
    const int warp = tid >> 5, lane = tid & 31;
    const int nbase = warp * 8, cbase = lane * 4;

    const int an0 = tid >> 3, an1 = (tid + 256) >> 3, af = tid & 7;
    const float4 f4z = make_float4(0.f, 0.f, 0.f, 0.f);

    auto ldA = [&](int kc, float4& r0, float4& r1) {
        const float4* Asrc = (kc < 4) ? (const float4*)g_agg : (const float4*)xin;
        int kb = (kc & 3) * 8;
        int gn0 = node0 + an0, gn1 = node0 + an1;
        r0 = (gn0 < NN) ? __ldg(&Asrc[(size_t)gn0 * 32 + kb + af]) : f4z;
        r1 = (gn1 < NN) ? __ldg(&Asrc[(size_t)gn1 * 32 + kb + af]) : f4z;
    };
    auto stA = [&](float4 r0, float4 r1) {
        int k0 = af * 4;
        Ach[(k0 + 0) * AS + an0] = r0.x; Ach[(k0 + 1) * AS + an0] = r0.y;
        Ach[(k0 + 2) * AS + an0] = r0.z; Ach[(k0 + 3) * AS + an0] = r0.w;
        Ach[(k0 + 0) * AS + an1] = r1.x; Ach[(k0 + 1) * AS + an1] = r1.y;
        Ach[(k0 + 2) * AS + an1] = r1.z; Ach[(k0 + 3) * AS + an1] = r1.w;
    };
    auto ldW = [&](int kc, float4* rw) {
        const float4* Wsrc = (kc < 4) ? (const float4*)Wl : (const float4*)Wr;
        int kr0 = (kc & 3) * KC;
        #pragma unroll
        for (int r = 0; r < 4; r++)
            rw[r] = __ldg(&Wsrc[(size_t)(kr0 + (tid >> 5) + 8 * r) * 32 + (tid & 31)]);
    };
    auto stW = [&](const float4* rw) {
        #pragma unroll
        for (int r = 0; r < 4; r++)
            ((float4*)Wch)[((tid >> 5) + 8 * r) * 32 + (tid & 31)] = rw[r];
    };

    float acc[8][4];
    #pragma unroll
    for (int i = 0; i < 8; i++)
        #pragma unroll
        for (int j = 0; j < 4; j++) acc[i][j] = 0.f;

    {
        float4 a0, a1, w0[4];
        ldA(0, a0, a1); ldW(0, w0);
        stA(a0, a1); stW(w0);
    }
    __syncthreads();

    for (int kc = 0; kc < 8; kc++) {
        float4 na0, na1, nw[4];
        if (kc < 7) { ldA(kc + 1, na0, na1); ldW(kc + 1, nw); }
        #pragma unroll 8
        for (int k = 0; k < KC; k++) {
            float4 A0 = *(const float4*)&Ach[k * AS + nbase];
            float4 A1 = *(const float4*)&Ach[k * AS + nbase + 4];
            float4 W4 = *(const float4*)&Wch[k * D + cbase];
            float a[8]  = {A0.x, A0.y, A0.z, A0.w, A1.x, A1.y, A1.z, A1.w};
            float w[4]  = {W4.x, W4.y, W4.z, W4.w};
            #pragma unroll
            for (int i = 0; i < 8; i++)
                #pragma unroll
                for (int j = 0; j < 4; j++)
                    acc[i][j] += a[i] * w[j];
        }
        __syncthreads();
        if (kc < 7) { stA(na0, na1); stW(nw); __syncthreads(); }
    }

    // Epilogue: + bl -> LN -> GELU -> + residual(x)
    float4 blv = __ldg(&((const float4*)bl)[lane]);
    float4 gv  = __ldg(&((const float4*)gma)[lane]);
    float4 bv  = __ldg(&((const float4*)bta)[lane]);
    float gvv[4]  = {gv.x, gv.y, gv.z, gv.w};
    float bvv[4]  = {bv.x, bv.y, bv.z, bv.w};
    float blvv[4] = {blv.x, blv.y, blv.z, blv.w};

    #pragma unroll
    for (int n = 0; n < 8; n++) {
        int gn = node0 + nbase + n;
        float h[4];
        #pragma unroll
        for (int j = 0; j < 4; j++) h[j] = acc[n][j] + blvv[j];
        float s1 = h[0] + h[1] + h[2] + h[3];
        float s2 = h[0]*h[0] + h[1]*h[1] + h[2]*h[2] + h[3]*h[3];
        #pragma unroll
        for (int off = 16; off; off >>= 1) {
            s1 += __shfl_xor_sync(0xffffffffu, s1, off);
            s2 += __shfl_xor_sync(0xffffffffu, s2, off);
        }
        float mu = s1 * (1.0f / 128.0f);
        float var = s2 * (1.0f / 128.0f) - mu * mu;
        float rstd = rsqrtf(var + 1e-5f);
        if (gn < NN) {
            float4 r = __ldg(&((const float4*)xin)[(size_t)gn * 32 + lane]);
            float rr[4] = {r.x, r.y, r.z, r.w};
            float o[4];
            #pragma unroll
            for (int j = 0; j < 4; j++) {
                float y = (h[j] - mu) * rstd * gvv[j] + bvv[j];
                o[j] = gelu_exact(y) + rr[j];
            }
            ((float4*)xout)[(size_t)gn * 32 + lane] = make_float4(o[0], o[1], o[2], o[3]);
        }
    }
}

// ---------------- p = x2 @ Wl3  (N x 128 @ 128 x 64) ----------------

__global__ __launch_bounds__(256) void gemm_p_kernel(const float* __restrict__ Wl3)
{
    extern __shared__ float sm[];
    float* Ws = sm;              // [128][64]
    float* Ax = Ws + D * DO;     // [128][AP]
    const int tid = threadIdx.x;
    const int node0 = blockIdx.x * 64;

    for (int i = tid; i < D * DO / 4; i += 256)
        ((float4*)Ws)[i] = __ldg(&((const float4*)Wl3)[i]);
    {
        int q = tid & 31, nl = tid >> 5;
        for (int nn = nl; nn < 64; nn += 8) {
            int gn = node0 + nn;
            float4 xv = make_float4(0.f, 0.f, 0.f, 0.f);
            if (gn < NN) xv = __ldg(&((const float4*)g_x2)[(size_t)gn * 32 + q]);
            int k = q * 4;
            Ax[(k + 0) * AP + nn] = xv.x; Ax[(k + 1) * AP + nn] = xv.y;
            Ax[(k + 2) * AP + nn] = xv.z; Ax[(k + 3) * AP + nn] = xv.w;
        }
    }
    __syncthreads();

    const int warp = tid >> 5, lane = tid & 31;
    const int nbase = warp * 8, c2 = lane * 2;
    float acc[8][2];
    #pragma unroll
    for (int i = 0; i < 8; i++) { acc[i][0] = 0.f; acc[i][1] = 0.f; }

    #pragma unroll 4
    for (int k = 0; k < D; k++) {
        float4 a0 = *(const float4*)&Ax[k * AP + nbase];
        float4 a1 = *(const float4*)&Ax[k * AP + nbase + 4];
        float2 w  = *(const float2*)&Ws[k * DO + c2];
        float a[8] = {a0.x, a0.y, a0.z, a0.w, a1.x, a1.y, a1.z, a1.w};
        #pragma unroll
        for (int i = 0; i < 8; i++) {
            acc[i][0] += a[i] * w.x;
            acc[i][1] += a[i] * w.y;
        }
    }
    #pragma unroll
    for (int n = 0; n < 8; n++) {
        int gn = node0 + nbase + n;
        if (gn < NN)
            ((float2*)g_p)[(size_t)gn * 32 + lane] = make_float2(acc[n][0], acc[n][1]);
    }
}

// -------- out stage, tiled: gelu(agg64 + bl3 + x2@Wr3) -> LN -> @Wc + bcls ------

__global__ __launch_bounds__(256) void out_block(
    const float* __restrict__ Wr3, const float* __restrict__ bl3,
    const float* __restrict__ gc, const float* __restrict__ bc,
    const float* __restrict__ Wc, const float* __restrict__ bcls,
    float* __restrict__ out)
{
    extern __shared__ float sm[];
    float* Wr3s = sm;                 // [128][64]   32KB
    float* Xs   = Wr3s + D * DO;      // [128][AS]   34.8KB (reused as Vs)
    float* Wcs  = Xs + D * AS;        // [64][40]    10KB
    float* bcs  = Wcs + DO * NC;      // [40]
    const int tid = threadIdx.x;
    const int node0 = blockIdx.x * 64;

    for (int i = tid; i < D * DO / 4; i += 256)
        ((float4*)Wr3s)[i] = __ldg(&((const float4*)Wr3)[i]);
    for (int i = tid; i < DO * NC; i += 256)
        Wcs[i] = __ldg(&Wc[i]);
    if (tid < NC) bcs[tid] = __ldg(&bcls[tid]);
    {
        int q = tid & 31, nl = tid >> 5;
        for (int nn = nl; nn < 64; nn += 8) {
            int gn = node0 + nn;
            float4 xv = make_float4(0.f, 0.f, 0.f, 0.f);
            if (gn < NN) xv = __ldg(&((const float4*)g_x2)[(size_t)gn * 32 + q]);
            int k = q * 4;
            Xs[(k + 0) * AS + nn] = xv.x; Xs[(k + 1) * AS + nn] = xv.y;
            Xs[(k + 2) * AS + nn] = xv.z; Xs[(k + 3) * AS + nn] = xv.w;
        }
    }
    __syncthreads();

    const int warp = tid >> 5, lane = tid & 31;
    const int nbase = warp * 8, c2 = lane * 2;
    float acc[8][2];
    #pragma unroll
    for (int i = 0; i < 8; i++) { acc[i][0] = 0.f; acc[i][1] = 0.f; }

    #pragma unroll 8
    for (int k = 0; k < D; k++) {
        float4 a0 = *(const float4*)&Xs[k * AS + nbase];
        float4 a1 = *(const float4*)&Xs[k * AS + nbase + 4];
        float2 w  = *(const float2*)&Wr3s[k * DO + c2];
        float a[8] = {a0.x, a0.y, a0.z, a0.w, a1.x, a1.y, a1.z, a1.w};
        #pragma unroll
        for (int i = 0; i < 8; i++) {
            acc[i][0] += a[i] * w.x;
            acc[i][1] += a[i] * w.y;
        }
    }
    __syncthreads();   // done reading Xs; reuse as Vs

    float* Vs = Xs;
    float2 b3v = __ldg(&((const float2*)bl3)[lane]);
    float2 gcv = __ldg(&((const float2*)gc)[lane]);
    float2 bcv = __ldg(&((const float2*)bc)[lane]);

    #pragma unroll
    for (int n = 0; n < 8; n++) {
        int gn = node0 + nbase + n;
        float2 ag = (gn < NN) ? __ldg(&((const float2*)g_agg64)[(size_t)gn * 32 + lane])
                              : make_float2(0.f, 0.f);
        float u0 = gelu_exact(acc[n][0] + b3v.x + ag.x);
        float u1 = gelu_exact(acc[n][1] + b3v.y + ag.y);
        float s1 = u0 + u1, s2 = u0 * u0 + u1 * u1;
        #pragma unroll
        for (int off = 16; off; off >>= 1) {
            s1 += __shfl_xor_sync(0xffffffffu, s1, off);
            s2 += __shfl_xor_sync(0xffffffffu, s2, off);
        }
        float mu = s1 * (1.0f / 64.0f);
        float var = s2 * (1.0f / 64.0f) - mu * mu;
        float rstd = rsqrtf(var + 1e-5f);
        Vs[(nbase + n) * AS + c2]     = (u0 - mu) * rstd * gcv.x + bcv.x;
        Vs[(nbase + n) * AS + c2 + 1] = (u1 - mu) * rstd * gcv.y + bcv.y;
    }
    __syncthreads();

    // classifier: 4 threads per node, 10 cols each
    int n = tid >> 2, cg = (tid & 3) * 10;
    float o[10];
    #pragma unroll
    for (int j = 0; j < 10; j++) o[j] = bcs[cg + j];
    #pragma unroll 8
    for (int k = 0; k < DO; k++) {
        float vv = Vs[n * AS + k];
        #pragma unroll
        for (int j = 0; j < 10; j++)
            o[j] += vv * Wcs[k * NC + cg + j];
    }
    int gn = node0 + n;
    if (gn < NN) {
        #pragma unroll
        for (int j = 0; j < 10; j++)
            out[(size_t)gn * NC + cg + j] = o[j];
    }
}

// ---------------- launcher ----------------

extern "C" void kernel_launch(void* const* d_in, const int* in_sizes, int n_in,
                              void* d_out, int out_size)
{
    const float* x    = (const float*)d_in[0];
    const int*   ei   = (const int*)d_in[1];
    const float* Wl1  = (const float*)d_in[2];
    const float* bl1  = (const float*)d_in[3];
    const float* Wr1  = (const float*)d_in[4];
    const float* g1   = (const float*)d_in[5];
    const float* b1   = (const float*)d_in[6];
    const float* Wl2  = (const float*)d_in[7];
    const float* bl2  = (const float*)d_in[8];
    const float* Wr2  = (const float*)d_in[9];
    const float* g2   = (const float*)d_in[10];
    const float* b2   = (const float*)d_in[11];
    const float* Wl3  = (const float*)d_in[12];
    const float* bl3  = (const float*)d_in[13];
    const float* Wr3  = (const float*)d_in[14];
    const float* gc   = (const float*)d_in[15];
    const float* bc   = (const float*)d_in[16];
    const float* Wc   = (const float*)d_in[17];
    const float* bcls = (const float*)d_in[18];
    const int* src = ei;
    const int* dst = ei + NE;
    float* out = (float*)d_out;

    void *p_x1 = nullptr, *p_x2 = nullptr;
    cudaGetSymbolAddress(&p_x1, g_x1);
    cudaGetSymbolAddress(&p_x2, g_x2);

    const size_t smem_p   = (size_t)(D * DO + D * AP) * sizeof(float);            // 67584 B
    const size_t smem_out = (size_t)(D * DO + D * AS + DO * NC + 48) * sizeof(float); // ~78KB
    cudaFuncSetAttribute(gemm_p_kernel, cudaFuncAttributeMaxDynamicSharedMemorySize, (int)smem_p);
    cudaFuncSetAttribute(out_block, cudaFuncAttributeMaxDynamicSharedMemorySize, (int)smem_out);

    const int nbn = (NN + 63) / 64;
    const int nbe = (NE + 255) / 256;
    const int nbw = ((NN * 32) + 255) / 256;   // one warp per node

    // CSR build
    zero_deg_cur<<<(NN + 255) / 256, 256>>>();
    count_deg<<<nbe, 256>>>(dst);
    scan_local<<<SCAN_B, SCAN_T>>>();
    scan_bsum<<<1, 128>>>();
    scan_add<<<(NN + 255) / 256, 256>>>();
    fill_edges<<<nbe, 256>>>(src, dst);

    // Layer 1
    gather128<<<nbw, 256>>>(x);
    sage_block2<<<nbn, 256>>>(x, Wl1, bl1, Wr1, g1, b1, (float*)p_x1);

    // Layer 2
    gather128<<<nbw, 256>>>((const float*)p_x1);
    sage_block2<<<nbn, 256>>>((const float*)p_x1, Wl2, bl2, Wr2, g2, b2, (float*)p_x2);

    // Layer 3: GEMM before aggregation (64-dim messages), then fused out stage
    gemm_p_kernel<<<nbn, 256, smem_p>>>(Wl3);
    gather64<<<nbw, 256>>>();
    out_block<<<nbn, 256, smem_out>>>(Wr3, bl3, gc, bc, Wc, bcls, out);
}

// round 5
// speedup vs baseline: 3.1357x; 1.2488x over previous
#include <cuda_runtime.h>
#include <math.h>
#include <stdint.h>

#define NN 50000
#define NE 800000
#define D  128
#define DO 64
#define NC 40
#define AP 68        // padded node-stride for fp32 transposed tiles (layer-3 kernels)
#define AS 68
#define ASTR 36      // A smem stride (tf32 path): [64 nodes][36]
#define WSTR 136     // W smem stride (tf32 path): [32 k][136]
#define SCAN_T 512
#define SCAN_B ((NN + SCAN_T - 1) / SCAN_T)   // 98

// Scratch (device globals: no allocation allowed)
__device__ float g_agg[(size_t)NN * D];
__device__ float g_x1[(size_t)NN * D];
__device__ float g_x2[(size_t)NN * D];
__device__ float g_p[(size_t)NN * DO];
__device__ float g_agg64[(size_t)NN * DO];
__device__ int   g_deg[NN];
__device__ int   g_off[NN];
__device__ int   g_cur[NN];
__device__ int   g_bsum[SCAN_B];
__device__ int   g_esrc[NE];

__device__ __forceinline__ float gelu_exact(float v) {
    return 0.5f * v * (1.0f + erff(v * 0.70710678118654752f));
}

__device__ __forceinline__ uint32_t f2tf32(float f) {
    uint32_t r;
    asm("cvt.rna.tf32.f32 %0, %1;" : "=r"(r) : "f"(f));
    return r;
}

__device__ __forceinline__ void mma_tf32(float* d,
    uint32_t a0, uint32_t a1, uint32_t a2, uint32_t a3,
    uint32_t b0, uint32_t b1)
{
    asm volatile(
        "mma.sync.aligned.m16n8k8.row.col.f32.tf32.tf32.f32 "
        "{%0,%1,%2,%3}, {%4,%5,%6,%7}, {%8,%9}, {%0,%1,%2,%3};"
        : "+f"(d[0]), "+f"(d[1]), "+f"(d[2]), "+f"(d[3])
        : "r"(a0), "r"(a1), "r"(a2), "r"(a3), "r"(b0), "r"(b1));
}

// ---------------- CSR build ----------------

__global__ void zero_deg_cur() {
    int i = blockIdx.x * blockDim.x + threadIdx.x;
    if (i < NN) { g_deg[i] = 0; g_cur[i] = 0; }
}

__global__ void count_deg(const int* __restrict__ dst) {
    int e = blockIdx.x * blockDim.x + threadIdx.x;
    if (e < NE) atomicAdd(&g_deg[dst[e]], 1);
}

__global__ void scan_local() {
    __shared__ int s[SCAN_T];
    int t = threadIdx.x;
    int i = blockIdx.x * SCAN_T + t;
    int v = (i < NN) ? g_deg[i] : 0;
    s[t] = v;
    __syncthreads();
    #pragma unroll
    for (int off = 1; off < SCAN_T; off <<= 1) {
        int a = (t >= off) ? s[t - off] : 0;
        __syncthreads();
        s[t] += a;
        __syncthreads();
    }
    if (i < NN) g_off[i] = s[t] - v;
    if (t == SCAN_T - 1) g_bsum[blockIdx.x] = s[t];
}

__global__ void scan_bsum() {
    __shared__ int s[128];
    int t = threadIdx.x;
    int v = (t < SCAN_B) ? g_bsum[t] : 0;
    s[t] = v;
    __syncthreads();
    #pragma unroll
    for (int off = 1; off < 128; off <<= 1) {
        int a = (t >= off) ? s[t - off] : 0;
        __syncthreads();
        s[t] += a;
        __syncthreads();
    }
    if (t < SCAN_B) g_bsum[t] = s[t] - v;
}

__global__ void scan_add() {
    int i = blockIdx.x * blockDim.x + threadIdx.x;
    if (i < NN) g_off[i] += g_bsum[i / SCAN_T];
}

__global__ void fill_edges(const int* __restrict__ src, const int* __restrict__ dst) {
    int e = blockIdx.x * blockDim.x + threadIdx.x;
    if (e >= NE) return;
    int d = dst[e];
    int pos = g_off[d] + atomicAdd(&g_cur[d], 1);
    g_esrc[pos] = src[e];
}

// ---------------- gather mean-aggregation (no atomics) ----------------

__global__ __launch_bounds__(256) void gather128(const float* __restrict__ x) {
    int gw = (blockIdx.x * blockDim.x + threadIdx.x) >> 5;
    int lane = threadIdx.x & 31;
    if (gw >= NN) return;
    int start = g_off[gw], deg = g_deg[gw];
    float4 acc = make_float4(0.f, 0.f, 0.f, 0.f);
    for (int base = 0; base < deg; base += 32) {
        int lim = min(32, deg - base);
        int idx = (lane < lim) ? __ldg(&g_esrc[start + base + lane]) : 0;
        for (int j = 0; j < lim; j++) {
            int s = __shfl_sync(0xffffffffu, idx, j);
            float4 v = __ldg(&((const float4*)x)[(size_t)s * 32 + lane]);
            acc.x += v.x; acc.y += v.y; acc.z += v.z; acc.w += v.w;
        }
    }
    float inv = 1.0f / fmaxf((float)deg, 1.0f);
    ((float4*)g_agg)[(size_t)gw * 32 + lane] =
        make_float4(acc.x * inv, acc.y * inv, acc.z * inv, acc.w * inv);
}

__global__ __launch_bounds__(256) void gather64() {
    int gw = (blockIdx.x * blockDim.x + threadIdx.x) >> 5;
    int lane = threadIdx.x & 31;
    if (gw >= NN) return;
    int start = g_off[gw], deg = g_deg[gw];
    float2 acc = make_float2(0.f, 0.f);
    for (int base = 0; base < deg; base += 32) {
        int lim = min(32, deg - base);
        int idx = (lane < lim) ? __ldg(&g_esrc[start + base + lane]) : 0;
        for (int j = 0; j < lim; j++) {
            int s = __shfl_sync(0xffffffffu, idx, j);
            float2 v = __ldg(&((const float2*)g_p)[(size_t)s * 32 + lane]);
            acc.x += v.x; acc.y += v.y;
        }
    }
    float inv = 1.0f / fmaxf((float)deg, 1.0f);
    ((float2*)g_agg64)[(size_t)gw * 32 + lane] = make_float2(acc.x * inv, acc.y * inv);
}

// ---- fused SAGE block v3: tf32 tensor-core GEMM (mma.sync m16n8k8) ----
// h = [agg; x] @ [Wl; Wr] + bl -> LN -> GELU -> + x.
// 64-node x 128-col tile. 8 warps: warpM=warp&3 (16-node group), warpN=warp>>2
// (64-col half). K streamed in chunks of 32; operands stored in smem as
// rna-rounded tf32 bits in conflict-free layouts.

__global__ __launch_bounds__(256, 2) void sage_tc(
    const float* __restrict__ xin,
    const float* __restrict__ Wl, const float* __restrict__ bl,
    const float* __restrict__ Wr,
    const float* __restrict__ gma, const float* __restrict__ bta,
    float* __restrict__ xout)
{
    __shared__ uint32_t As[64 * ASTR];       // [node][k]  9216 B
    __shared__ uint32_t Ws[32 * WSTR];       // [k][n]    17408 B
    __shared__ float sred[2][64][2];         // per-wn partial LN sums

    const int tid = threadIdx.x;
    const int node0 = blockIdx.x * 64;
    const int warp = tid >> 5, lane = tid & 31;
    const int wm = warp & 3, wn = warp >> 2;
    const int g = lane >> 2, t4 = lane & 3;

    const int an0 = tid >> 3, an1 = (tid + 256) >> 3, af = tid & 7;
    const float4 f4z = make_float4(0.f, 0.f, 0.f, 0.f);

    auto ldA = [&](int kc, float4& r0, float4& r1) {
        const float4* Asrc = (kc < 4) ? (const float4*)g_agg : (const float4*)xin;
        int kb = (kc & 3) * 8;
        int gn0 = node0 + an0, gn1 = node0 + an1;
        r0 = (gn0 < NN) ? __ldg(&Asrc[(size_t)gn0 * 32 + kb + af]) : f4z;
        r1 = (gn1 < NN) ? __ldg(&Asrc[(size_t)gn1 * 32 + kb + af]) : f4z;
    };
    auto stA = [&](float4 r0, float4 r1) {
        uint4 u0 = make_uint4(f2tf32(r0.x), f2tf32(r0.y), f2tf32(r0.z), f2tf32(r0.w));
        uint4 u1 = make_uint4(f2tf32(r1.x), f2tf32(r1.y), f2tf32(r1.z), f2tf32(r1.w));
        *(uint4*)&As[an0 * ASTR + af * 4] = u0;
        *(uint4*)&As[an1 * ASTR + af * 4] = u1;
    };
    auto ldW = [&](int kc, float4* rw) {
        const float4* Wsrc = (kc < 4) ? (const float4*)Wl : (const float4*)Wr;
        int kr0 = (kc & 3) * 32;
        #pragma unroll
        for (int r = 0; r < 4; r++)
            rw[r] = __ldg(&Wsrc[(size_t)(kr0 + warp + 8 * r) * 32 + lane]);
    };
    auto stW = [&](const float4* rw) {
        #pragma unroll
        for (int r = 0; r < 4; r++) {
            uint4 u = make_uint4(f2tf32(rw[r].x), f2tf32(rw[r].y),
                                 f2tf32(rw[r].z), f2tf32(rw[r].w));
            *(uint4*)&Ws[(warp + 8 * r) * WSTR + lane * 4] = u;
        }
    };

    float acc[8][4];
    #pragma unroll
    for (int i = 0; i < 8; i++)
        #pragma unroll
        for (int j = 0; j < 4; j++) acc[i][j] = 0.f;

    {
        float4 a0, a1, w0[4];
        ldA(0, a0, a1); ldW(0, w0);
        stA(a0, a1); stW(w0);
    }
    __syncthreads();

    const int arow = wm * 16 + g;
    for (int kc = 0; kc < 8; kc++) {
        float4 na0, na1, nw[4];
        if (kc < 7) { ldA(kc + 1, na0, na1); ldW(kc + 1, nw); }
        #pragma unroll
        for (int kk = 0; kk < 4; kk++) {
            uint32_t a0 = As[arow * ASTR + kk * 8 + t4];
            uint32_t a1 = As[(arow + 8) * ASTR + kk * 8 + t4];
            uint32_t a2 = As[arow * ASTR + kk * 8 + t4 + 4];
            uint32_t a3 = As[(arow + 8) * ASTR + kk * 8 + t4 + 4];
            #pragma unroll
            for (int nt = 0; nt < 8; nt++) {
                int ncol = wn * 64 + nt * 8 + g;
                uint32_t b0 = Ws[(kk * 8 + t4) * WSTR + ncol];
                uint32_t b1 = Ws[(kk * 8 + t4 + 4) * WSTR + ncol];
                mma_tf32(acc[nt], a0, a1, a2, a3, b0, b1);
            }
        }
        __syncthreads();
        if (kc < 7) { stA(na0, na1); stW(nw); __syncthreads(); }
    }

    // ---- epilogue: + bl -> LN (across 128 cols) -> GELU -> + residual ----
    float s1a = 0.f, s2a = 0.f, s1b = 0.f, s2b = 0.f;
    #pragma unroll
    for (int nt = 0; nt < 8; nt++) {
        int c = wn * 64 + nt * 8 + 2 * t4;
        float2 blv = *(const float2*)&bl[c];
        acc[nt][0] += blv.x; acc[nt][1] += blv.y;
        acc[nt][2] += blv.x; acc[nt][3] += blv.y;
        s1a += acc[nt][0] + acc[nt][1];
        s2a += acc[nt][0] * acc[nt][0] + acc[nt][1] * acc[nt][1];
        s1b += acc[nt][2] + acc[nt][3];
        s2b += acc[nt][2] * acc[nt][2] + acc[nt][3] * acc[nt][3];
    }
    #pragma unroll
    for (int off = 1; off <= 2; off <<= 1) {
        s1a += __shfl_xor_sync(0xffffffffu, s1a, off);
        s2a += __shfl_xor_sync(0xffffffffu, s2a, off);
        s1b += __shfl_xor_sync(0xffffffffu, s1b, off);
        s2b += __shfl_xor_sync(0xffffffffu, s2b, off);
    }
    if (t4 == 0) {
        sred[wn][wm * 16 + g][0] = s1a;      sred[wn][wm * 16 + g][1] = s2a;
        sred[wn][wm * 16 + 8 + g][0] = s1b;  sred[wn][wm * 16 + 8 + g][1] = s2b;
    }
    __syncthreads();

    float S1a = sred[0][wm * 16 + g][0] + sred[1][wm * 16 + g][0];
    float S2a = sred[0][wm * 16 + g][1] + sred[1][wm * 16 + g][1];
    float S1b = sred[0][wm * 16 + 8 + g][0] + sred[1][wm * 16 + 8 + g][0];
    float S2b = sred[0][wm * 16 + 8 + g][1] + sred[1][wm * 16 + 8 + g][1];
    float mua = S1a * (1.0f / 128.0f);
    float vara = S2a * (1.0f / 128.0f) - mua * mua;
    float rsa = rsqrtf(vara + 1e-5f);
    float mub = S1b * (1.0f / 128.0f);
    float varb = S2b * (1.0f / 128.0f) - mub * mub;
    float rsb = rsqrtf(varb + 1e-5f);

    const int gna = node0 + wm * 16 + g;
    const int gnb = gna + 8;
    #pragma unroll
    for (int nt = 0; nt < 8; nt++) {
        int c = wn * 64 + nt * 8 + 2 * t4;
        float2 gv = *(const float2*)&gma[c];
        float2 bv = *(const float2*)&bta[c];
        if (gna < NN) {
            float2 r = *(const float2*)&xin[(size_t)gna * D + c];
            float o0 = gelu_exact((acc[nt][0] - mua) * rsa * gv.x + bv.x) + r.x;
            float o1 = gelu_exact((acc[nt][1] - mua) * rsa * gv.y + bv.y) + r.y;
            *(float2*)&xout[(size_t)gna * D + c] = make_float2(o0, o1);
        }
        if (gnb < NN) {
            float2 r = *(const float2*)&xin[(size_t)gnb * D + c];
            float o0 = gelu_exact((acc[nt][2] - mub) * rsb * gv.x + bv.x) + r.x;
            float o1 = gelu_exact((acc[nt][3] - mub) * rsb * gv.y + bv.y) + r.y;
            *(float2*)&xout[(size_t)gnb * D + c] = make_float2(o0, o1);
        }
    }
}

// ---------------- p = x2 @ Wl3  (N x 128 @ 128 x 64), fp32 ----------------

__global__ __launch_bounds__(256) void gemm_p_kernel(const float* __restrict__ Wl3)
{
    extern __shared__ float sm[];
    float* Wsh = sm;             // [128][64]
    float* Ax = Wsh + D * DO;    // [128][AP]
    const int tid = threadIdx.x;
    const int node0 = blockIdx.x * 64;

    for (int i = tid; i < D * DO / 4; i += 256)
        ((float4*)Wsh)[i] = __ldg(&((const float4*)Wl3)[i]);
    {
        int q = tid & 31, nl = tid >> 5;
        for (int nn = nl; nn < 64; nn += 8) {
            int gn = node0 + nn;
            float4 xv = make_float4(0.f, 0.f, 0.f, 0.f);
            if (gn < NN) xv = __ldg(&((const float4*)g_x2)[(size_t)gn * 32 + q]);
            int k = q * 4;
            Ax[(k + 0) * AP + nn] = xv.x; Ax[(k + 1) * AP + nn] = xv.y;
            Ax[(k + 2) * AP + nn] = xv.z; Ax[(k + 3) * AP + nn] = xv.w;
        }
    }
    __syncthreads();

    const int warp = tid >> 5, lane = tid & 31;
    const int nbase = warp * 8, c2 = lane * 2;
    float acc[8][2];
    #pragma unroll
    for (int i = 0; i < 8; i++) { acc[i][0] = 0.f; acc[i][1] = 0.f; }

    #pragma unroll 4
    for (int k = 0; k < D; k++) {
        float4 a0 = *(const float4*)&Ax[k * AP + nbase];
        float4 a1 = *(const float4*)&Ax[k * AP + nbase + 4];
        float2 w  = *(const float2*)&Wsh[k * DO + c2];
        float a[8] = {a0.x, a0.y, a0.z, a0.w, a1.x, a1.y, a1.z, a1.w};
        #pragma unroll
        for (int i = 0; i < 8; i++) {
            acc[i][0] += a[i] * w.x;
            acc[i][1] += a[i] * w.y;
        }
    }
    #pragma unroll
    for (int n = 0; n < 8; n++) {
        int gn = node0 + nbase + n;
        if (gn < NN)
            ((float2*)g_p)[(size_t)gn * 32 + lane] = make_float2(acc[n][0], acc[n][1]);
    }
}

// -------- out stage, tiled: gelu(agg64 + bl3 + x2@Wr3) -> LN -> @Wc + bcls ------

__global__ __launch_bounds__(256) void out_block(
    const float* __restrict__ Wr3, const float* __restrict__ bl3,
    const float* __restrict__ gc, const float* __restrict__ bc,
    const float* __restrict__ Wc, const float* __restrict__ bcls,
    float* __restrict__ out)
{
    extern __shared__ float sm[];
    float* Wr3s = sm;                 // [128][64]
    float* Xs   = Wr3s + D * DO;      // [128][AS] (reused as Vs)
    float* Wcs  = Xs + D * AS;        // [64][40]
    float* bcs  = Wcs + DO * NC;      // [40]
    const int tid = threadIdx.x;
    const int node0 = blockIdx.x * 64;

    for (int i = tid; i < D * DO / 4; i += 256)
        ((float4*)Wr3s)[i] = __ldg(&((const float4*)Wr3)[i]);
    for (int i = tid; i < DO * NC; i += 256)
        Wcs[i] = __ldg(&Wc[i]);
    if (tid < NC) bcs[tid] = __ldg(&bcls[tid]);
    {
        int q = tid & 31, nl = tid >> 5;
        for (int nn = nl; nn < 64; nn += 8) {
            int gn = node0 + nn;
            float4 xv = make_float4(0.f, 0.f, 0.f, 0.f);
            if (gn < NN) xv = __ldg(&((const float4*)g_x2)[(size_t)gn * 32 + q]);
            int k = q * 4;
            Xs[(k + 0) * AS + nn] = xv.x; Xs[(k + 1) * AS + nn] = xv.y;
            Xs[(k + 2) * AS + nn] = xv.z; Xs[(k + 3) * AS + nn] = xv.w;
        }
    }
    __syncthreads();

    const int warp = tid >> 5, lane = tid & 31;
    const int nbase = warp * 8, c2 = lane * 2;
    float acc[8][2];
    #pragma unroll
    for (int i = 0; i < 8; i++) { acc[i][0] = 0.f; acc[i][1] = 0.f; }

    #pragma unroll 8
    for (int k = 0; k < D; k++) {
        float4 a0 = *(const float4*)&Xs[k * AS + nbase];
        float4 a1 = *(const float4*)&Xs[k * AS + nbase + 4];
        float2 w  = *(const float2*)&Wr3s[k * DO + c2];
        float a[8] = {a0.x, a0.y, a0.z, a0.w, a1.x, a1.y, a1.z, a1.w};
        #pragma unroll
        for (int i = 0; i < 8; i++) {
            acc[i][0] += a[i] * w.x;
            acc[i][1] += a[i] * w.y;
        }
    }
    __syncthreads();   // done reading Xs; reuse as Vs

    float* Vs = Xs;
    float2 b3v = __ldg(&((const float2*)bl3)[lane]);
    float2 gcv = __ldg(&((const float2*)gc)[lane]);
    float2 bcv = __ldg(&((const float2*)bc)[lane]);

    #pragma unroll
    for (int n = 0; n < 8; n++) {
        int gn = node0 + nbase + n;
        float2 ag = (gn < NN) ? __ldg(&((const float2*)g_agg64)[(size_t)gn * 32 + lane])
                              : make_float2(0.f, 0.f);
        float u0 = gelu_exact(acc[n][0] + b3v.x + ag.x);
        float u1 = gelu_exact(acc[n][1] + b3v.y + ag.y);
        float s1 = u0 + u1, s2 = u0 * u0 + u1 * u1;
        #pragma unroll
        for (int off = 16; off; off >>= 1) {
            s1 += __shfl_xor_sync(0xffffffffu, s1, off);
            s2 += __shfl_xor_sync(0xffffffffu, s2, off);
        }
        float mu = s1 * (1.0f / 64.0f);
        float var = s2 * (1.0f / 64.0f) - mu * mu;
        float rstd = rsqrtf(var + 1e-5f);
        Vs[(nbase + n) * AS + c2]     = (u0 - mu) * rstd * gcv.x + bcv.x;
        Vs[(nbase + n) * AS + c2 + 1] = (u1 - mu) * rstd * gcv.y + bcv.y;
    }
    __syncthreads();

    int n = tid >> 2, cg = (tid & 3) * 10;
    float o[10];
    #pragma unroll
    for (int j = 0; j < 10; j++) o[j] = bcs[cg + j];
    #pragma unroll 8
    for (int k = 0; k < DO; k++) {
        float vv = Vs[n * AS + k];
        #pragma unroll
        for (int j = 0; j < 10; j++)
            o[j] += vv * Wcs[k * NC + cg + j];
    }
    int gn = node0 + n;
    if (gn < NN) {
        #pragma unroll
        for (int j = 0; j < 10; j++)
            out[(size_t)gn * NC + cg + j] = o[j];
    }
}

// ---------------- launcher ----------------

extern "C" void kernel_launch(void* const* d_in, const int* in_sizes, int n_in,
                              void* d_out, int out_size)
{
    const float* x    = (const float*)d_in[0];
    const int*   ei   = (const int*)d_in[1];
    const float* Wl1  = (const float*)d_in[2];
    const float* bl1  = (const float*)d_in[3];
    const float* Wr1  = (const float*)d_in[4];
    const float* g1   = (const float*)d_in[5];
    const float* b1   = (const float*)d_in[6];
    const float* Wl2  = (const float*)d_in[7];
    const float* bl2  = (const float*)d_in[8];
    const float* Wr2  = (const float*)d_in[9];
    const float* b2g  = (const float*)d_in[10];
    const float* b2   = (const float*)d_in[11];
    const float* Wl3  = (const float*)d_in[12];
    const float* bl3  = (const float*)d_in[13];
    const float* Wr3  = (const float*)d_in[14];
    const float* gc   = (const float*)d_in[15];
    const float* bc   = (const float*)d_in[16];
    const float* Wc   = (const float*)d_in[17];
    const float* bcls = (const float*)d_in[18];
    const int* src = ei;
    const int* dst = ei + NE;
    float* out = (float*)d_out;

    void *p_x1 = nullptr, *p_x2 = nullptr;
    cudaGetSymbolAddress(&p_x1, g_x1);
    cudaGetSymbolAddress(&p_x2, g_x2);

    const size_t smem_p   = (size_t)(D * DO + D * AP) * sizeof(float);
    const size_t smem_out = (size_t)(D * DO + D * AS + DO * NC + 48) * sizeof(float);
    cudaFuncSetAttribute(gemm_p_kernel, cudaFuncAttributeMaxDynamicSharedMemorySize, (int)smem_p);
    cudaFuncSetAttribute(out_block, cudaFuncAttributeMaxDynamicSharedMemorySize, (int)smem_out);

    const int nbn = (NN + 63) / 64;
    const int nbe = (NE + 255) / 256;
    const int nbw = ((NN * 32) + 255) / 256;   // one warp per node

    // CSR build
    zero_deg_cur<<<(NN + 255) / 256, 256>>>();
    count_deg<<<nbe, 256>>>(dst);
    scan_local<<<SCAN_B, SCAN_T>>>();
    scan_bsum<<<1, 128>>>();
    scan_add<<<(NN + 255) / 256, 256>>>();
    fill_edges<<<nbe, 256>>>(src, dst);

    // Layer 1
    gather128<<<nbw, 256>>>(x);
    sage_tc<<<nbn, 256>>>(x, Wl1, bl1, Wr1, g1, b1, (float*)p_x1);

    // Layer 2
    gather128<<<nbw, 256>>>((const float*)p_x1);
    sage_tc<<<nbn, 256>>>((const float*)p_x1, Wl2, bl2, Wr2, b2g, b2, (float*)p_x2);

    // Layer 3: GEMM before aggregation (64-dim messages), then fused out stage
    gemm_p_kernel<<<nbn, 256, smem_p>>>(Wl3);
    gather64<<<nbw, 256>>>();
    out_block<<<nbn, 256, smem_out>>>(Wr3, bl3, gc, bc, Wc, bcls, out);
}

// round 6
// speedup vs baseline: 3.6551x; 1.1656x over previous
#include <cuda_runtime.h>
#include <math.h>
#include <stdint.h>

#define NN 50000
#define NE 800000
#define D  128
#define DO 64
#define NC 40
#define SCAN_T 512
#define SCAN_B ((NN + SCAN_T - 1) / SCAN_T)   // 98

// Scratch (device globals: no allocation allowed)
__device__ float g_agg[(size_t)NN * D];
__device__ float g_x1[(size_t)NN * D];
__device__ float g_x2[(size_t)NN * D];
__device__ float g_p[(size_t)NN * DO];
__device__ float g_q[(size_t)NN * DO];
__device__ float g_agg64[(size_t)NN * DO];
__device__ int   g_deg[NN];
__device__ int   g_off[NN];
__device__ int   g_cur[NN];
__device__ int   g_bsum[SCAN_B];
__device__ int   g_esrc[NE];

__device__ __forceinline__ float gelu_exact(float v) {
    return 0.5f * v * (1.0f + erff(v * 0.70710678118654752f));
}

__device__ __forceinline__ uint32_t f2tf32(float f) {
    uint32_t r;
    asm("cvt.rna.tf32.f32 %0, %1;" : "=r"(r) : "f"(f));
    return r;
}

__device__ __forceinline__ void mma_tf32(float* d,
    uint32_t a0, uint32_t a1, uint32_t a2, uint32_t a3,
    uint32_t b0, uint32_t b1)
{
    asm volatile(
        "mma.sync.aligned.m16n8k8.row.col.f32.tf32.tf32.f32 "
        "{%0,%1,%2,%3}, {%4,%5,%6,%7}, {%8,%9}, {%0,%1,%2,%3};"
        : "+f"(d[0]), "+f"(d[1]), "+f"(d[2]), "+f"(d[3])
        : "r"(a0), "r"(a1), "r"(a2), "r"(a3), "r"(b0), "r"(b1));
}

// ---------------- CSR build ----------------

__global__ void zero_deg_cur() {
    int i = blockIdx.x * blockDim.x + threadIdx.x;
    if (i < NN) { g_deg[i] = 0; g_cur[i] = 0; }
}

__global__ void count_deg(const int* __restrict__ dst) {
    int e = blockIdx.x * blockDim.x + threadIdx.x;
    if (e < NE) atomicAdd(&g_deg[dst[e]], 1);
}

__global__ void scan_local() {
    __shared__ int s[SCAN_T];
    int t = threadIdx.x;
    int i = blockIdx.x * SCAN_T + t;
    int v = (i < NN) ? g_deg[i] : 0;
    s[t] = v;
    __syncthreads();
    #pragma unroll
    for (int off = 1; off < SCAN_T; off <<= 1) {
        int a = (t >= off) ? s[t - off] : 0;
        __syncthreads();
        s[t] += a;
        __syncthreads();
    }
    if (i < NN) g_off[i] = s[t] - v;
    if (t == SCAN_T - 1) g_bsum[blockIdx.x] = s[t];
}

__global__ void scan_bsum() {
    __shared__ int s[128];
    int t = threadIdx.x;
    int v = (t < SCAN_B) ? g_bsum[t] : 0;
    s[t] = v;
    __syncthreads();
    #pragma unroll
    for (int off = 1; off < 128; off <<= 1) {
        int a = (t >= off) ? s[t - off] : 0;
        __syncthreads();
        s[t] += a;
        __syncthreads();
    }
    if (t < SCAN_B) g_bsum[t] = s[t] - v;
}

__global__ void scan_add() {
    int i = blockIdx.x * blockDim.x + threadIdx.x;
    if (i < NN) g_off[i] += g_bsum[i / SCAN_T];
}

__global__ void fill_edges(const int* __restrict__ src, const int* __restrict__ dst) {
    int e = blockIdx.x * blockDim.x + threadIdx.x;
    if (e >= NE) return;
    int d = dst[e];
    int pos = g_off[d] + atomicAdd(&g_cur[d], 1);
    g_esrc[pos] = src[e];
}

// ---------------- gather mean-aggregation (warp/node, 4-way unrolled) --------

__global__ __launch_bounds__(256) void gather128(const float* __restrict__ x) {
    int gw = (blockIdx.x * blockDim.x + threadIdx.x) >> 5;
    int lane = threadIdx.x & 31;
    if (gw >= NN) return;
    int start = g_off[gw], deg = g_deg[gw];
    const int* es = g_esrc + start;
    const float4* x4 = (const float4*)x;
    float4 a0 = make_float4(0.f,0.f,0.f,0.f), a1 = a0, a2 = a0, a3 = a0;
    int e = 0;
    for (; e + 4 <= deg; e += 4) {
        int s0 = __ldg(es + e),     s1 = __ldg(es + e + 1);
        int s2 = __ldg(es + e + 2), s3 = __ldg(es + e + 3);
        float4 v0 = __ldg(&x4[(size_t)s0 * 32 + lane]);
        float4 v1 = __ldg(&x4[(size_t)s1 * 32 + lane]);
        float4 v2 = __ldg(&x4[(size_t)s2 * 32 + lane]);
        float4 v3 = __ldg(&x4[(size_t)s3 * 32 + lane]);
        a0.x += v0.x; a0.y += v0.y; a0.z += v0.z; a0.w += v0.w;
        a1.x += v1.x; a1.y += v1.y; a1.z += v1.z; a1.w += v1.w;
        a2.x += v2.x; a2.y += v2.y; a2.z += v2.z; a2.w += v2.w;
        a3.x += v3.x; a3.y += v3.y; a3.z += v3.z; a3.w += v3.w;
    }
    for (; e < deg; e++) {
        int s0 = __ldg(es + e);
        float4 v0 = __ldg(&x4[(size_t)s0 * 32 + lane]);
        a0.x += v0.x; a0.y += v0.y; a0.z += v0.z; a0.w += v0.w;
    }
    float inv = 1.0f / fmaxf((float)deg, 1.0f);
    float4 r;
    r.x = (a0.x + a1.x + a2.x + a3.x) * inv;
    r.y = (a0.y + a1.y + a2.y + a3.y) * inv;
    r.z = (a0.z + a1.z + a2.z + a3.z) * inv;
    r.w = (a0.w + a1.w + a2.w + a3.w) * inv;
    ((float4*)g_agg)[(size_t)gw * 32 + lane] = r;
}

__global__ __launch_bounds__(256) void gather64() {
    int gw = (blockIdx.x * blockDim.x + threadIdx.x) >> 5;
    int lane = threadIdx.x & 31;
    if (gw >= NN) return;
    int start = g_off[gw], deg = g_deg[gw];
    const int* es = g_esrc + start;
    const float2* p2 = (const float2*)g_p;
    float2 a0 = make_float2(0.f,0.f), a1 = a0, a2 = a0, a3 = a0;
    int e = 0;
    for (; e + 4 <= deg; e += 4) {
        int s0 = __ldg(es + e),     s1 = __ldg(es + e + 1);
        int s2 = __ldg(es + e + 2), s3 = __ldg(es + e + 3);
        float2 v0 = __ldg(&p2[(size_t)s0 * 32 + lane]);
        float2 v1 = __ldg(&p2[(size_t)s1 * 32 + lane]);
        float2 v2 = __ldg(&p2[(size_t)s2 * 32 + lane]);
        float2 v3 = __ldg(&p2[(size_t)s3 * 32 + lane]);
        a0.x += v0.x; a0.y += v0.y;
        a1.x += v1.x; a1.y += v1.y;
        a2.x += v2.x; a2.y += v2.y;
        a3.x += v3.x; a3.y += v3.y;
    }
    for (; e < deg; e++) {
        int s0 = __ldg(es + e);
        float2 v0 = __ldg(&p2[(size_t)s0 * 32 + lane]);
        a0.x += v0.x; a0.y += v0.y;
    }
    float inv = 1.0f / fmaxf((float)deg, 1.0f);
    ((float2*)g_agg64)[(size_t)gw * 32 + lane] =
        make_float2((a0.x + a1.x + a2.x + a3.x) * inv,
                    (a0.y + a1.y + a2.y + a3.y) * inv);
}

// ---- fused SAGE block v4: tf32 mma, 32x32 warp tiles, paired uint2 operands ----
// h = [agg; x] @ [Wl; Wr] + bl -> LN -> GELU -> + x.
// Block: 64 nodes x 128 cols; 8 warps: wm=warp&1 (32 nodes), wn=warp>>1 (32 cols).
// K streamed in chunks of 32. Paired smem layouts: one 64-bit LDS per fragment.

#define ASTR2 20   // uint2 stride per node (16 used + 4 pad)
#define WSTR2 132  // uint2 stride per pair-row (128 used + 4 pad)

__global__ __launch_bounds__(256, 2) void sage_tc2(
    const float* __restrict__ xin,
    const float* __restrict__ Wl, const float* __restrict__ bl,
    const float* __restrict__ Wr,
    const float* __restrict__ gma, const float* __restrict__ bta,
    float* __restrict__ xout)
{
    __shared__ uint2 Apk[64 * ASTR2];     // 10240 B
    __shared__ uint2 Wpk[16 * WSTR2];     // 16896 B
    __shared__ float sred[4][64][2];      //  2048 B

    const int tid = threadIdx.x;
    const int node0 = blockIdx.x * 64;
    const int warp = tid >> 5, lane = tid & 31;
    const int wm = warp & 1, wn = warp >> 1;
    const int g = lane >> 2, t4 = lane & 3;

    const int an0 = tid >> 3, an1 = (tid + 256) >> 3, af = tid & 7;
    const int koff = (af >> 1) * 8 + (af & 1);   // uint-offset base for paired A store
    const float4 f4z = make_float4(0.f, 0.f, 0.f, 0.f);

    auto ldA = [&](int kc, float4& r0, float4& r1) {
        const float4* Asrc = (kc < 4) ? (const float4*)g_agg : (const float4*)xin;
        int kb = (kc & 3) * 8;
        int gn0 = node0 + an0, gn1 = node0 + an1;
        r0 = (gn0 < NN) ? __ldg(&Asrc[(size_t)gn0 * 32 + kb + af]) : f4z;
        r1 = (gn1 < NN) ? __ldg(&Asrc[(size_t)gn1 * 32 + kb + af]) : f4z;
    };
    auto stA = [&](float4 r0, float4 r1) {
        uint32_t* Au = (uint32_t*)Apk;
        Au[an0 * 40 + koff + 0] = f2tf32(r0.x);
        Au[an0 * 40 + koff + 2] = f2tf32(r0.y);
        Au[an0 * 40 + koff + 4] = f2tf32(r0.z);
        Au[an0 * 40 + koff + 6] = f2tf32(r0.w);
        Au[an1 * 40 + koff + 0] = f2tf32(r1.x);
        Au[an1 * 40 + koff + 2] = f2tf32(r1.y);
        Au[an1 * 40 + koff + 4] = f2tf32(r1.z);
        Au[an1 * 40 + koff + 6] = f2tf32(r1.w);
    };
    auto ldW = [&](int kc, float4* w) {
        const float4* Wsrc = (kc < 4) ? (const float4*)Wl : (const float4*)Wr;
        int kr0 = (kc & 3) * 32;
        int p0 = 2 * warp, p1 = 2 * warp + 1;
        int k0 = (p0 >> 2) * 8 + (p0 & 3);
        int k1 = (p1 >> 2) * 8 + (p1 & 3);
        w[0] = __ldg(&Wsrc[(size_t)(kr0 + k0) * 32 + lane]);
        w[1] = __ldg(&Wsrc[(size_t)(kr0 + k0 + 4) * 32 + lane]);
        w[2] = __ldg(&Wsrc[(size_t)(kr0 + k1) * 32 + lane]);
        w[3] = __ldg(&Wsrc[(size_t)(kr0 + k1 + 4) * 32 + lane]);
    };
    auto stW = [&](const float4* w) {
        uint4* W4 = (uint4*)Wpk;
        #pragma unroll
        for (int q = 0; q < 2; q++) {
            int p = 2 * warp + q;
            float4 lo = w[2 * q], hi = w[2 * q + 1];
            W4[p * 66 + 2 * lane]     = make_uint4(f2tf32(lo.x), f2tf32(hi.x),
                                                   f2tf32(lo.y), f2tf32(hi.y));
            W4[p * 66 + 2 * lane + 1] = make_uint4(f2tf32(lo.z), f2tf32(hi.z),
                                                   f2tf32(lo.w), f2tf32(hi.w));
        }
    };

    float acc0[4][4], acc1[4][4];
    #pragma unroll
    for (int i = 0; i < 4; i++)
        #pragma unroll
        for (int j = 0; j < 4; j++) { acc0[i][j] = 0.f; acc1[i][j] = 0.f; }

    {
        float4 a0, a1, w0[4];
        ldA(0, a0, a1); ldW(0, w0);
        stA(a0, a1); stW(w0);
    }
    __syncthreads();

    const int C = wm * 32;
    for (int kc = 0; kc < 8; kc++) {
        float4 na0, na1, nw[4];
        if (kc < 7) { ldA(kc + 1, na0, na1); ldW(kc + 1, nw); }
        #pragma unroll
        for (int kk = 0; kk < 4; kk++) {
            int pbase = kk * 4 + t4;
            uint2 qa0 = Apk[(C + g)      * ASTR2 + pbase];
            uint2 qa1 = Apk[(C + g + 8)  * ASTR2 + pbase];
            uint2 qa2 = Apk[(C + g + 16) * ASTR2 + pbase];
            uint2 qa3 = Apk[(C + g + 24) * ASTR2 + pbase];
            #pragma unroll
            for (int nt = 0; nt < 4; nt++) {
                uint2 qb = Wpk[pbase * WSTR2 + wn * 32 + nt * 8 + g];
                mma_tf32(acc0[nt], qa0.x, qa1.x, qa0.y, qa1.y, qb.x, qb.y);
                mma_tf32(acc1[nt], qa2.x, qa3.x, qa2.y, qa3.y, qb.x, qb.y);
            }
        }
        __syncthreads();
        if (kc < 7) { stA(na0, na1); stW(nw); __syncthreads(); }
    }

    // ---- epilogue: + bl -> LN (128 cols) -> GELU -> + residual ----
    float s[4][2];
    #pragma unroll
    for (int r = 0; r < 4; r++) { s[r][0] = 0.f; s[r][1] = 0.f; }
    #pragma unroll
    for (int nt = 0; nt < 4; nt++) {
        int c = wn * 32 + nt * 8 + 2 * t4;
        float2 blv = *(const float2*)&bl[c];
        acc0[nt][0] += blv.x; acc0[nt][1] += blv.y;
        acc0[nt][2] += blv.x; acc0[nt][3] += blv.y;
        acc1[nt][0] += blv.x; acc1[nt][1] += blv.y;
        acc1[nt][2] += blv.x; acc1[nt][3] += blv.y;
        s[0][0] += acc0[nt][0] + acc0[nt][1];
        s[0][1] += acc0[nt][0]*acc0[nt][0] + acc0[nt][1]*acc0[nt][1];
        s[1][0] += acc0[nt][2] + acc0[nt][3];
        s[1][1] += acc0[nt][2]*acc0[nt][2] + acc0[nt][3]*acc0[nt][3];
        s[2][0] += acc1[nt][0] + acc1[nt][1];
        s[2][1] += acc1[nt][0]*acc1[nt][0] + acc1[nt][1]*acc1[nt][1];
        s[3][0] += acc1[nt][2] + acc1[nt][3];
        s[3][1] += acc1[nt][2]*acc1[nt][2] + acc1[nt][3]*acc1[nt][3];
    }
    #pragma unroll
    for (int off = 1; off <= 2; off <<= 1)
        #pragma unroll
        for (int r = 0; r < 4; r++) {
            s[r][0] += __shfl_xor_sync(0xffffffffu, s[r][0], off);
            s[r][1] += __shfl_xor_sync(0xffffffffu, s[r][1], off);
        }
    if (t4 == 0) {
        #pragma unroll
        for (int r = 0; r < 4; r++) {
            sred[wn][C + g + r * 8][0] = s[r][0];
            sred[wn][C + g + r * 8][1] = s[r][1];
        }
    }
    __syncthreads();

    float mu[4], rs[4];
    #pragma unroll
    for (int r = 0; r < 4; r++) {
        int row = C + g + r * 8;
        float S1 = sred[0][row][0] + sred[1][row][0] + sred[2][row][0] + sred[3][row][0];
        float S2 = sred[0][row][1] + sred[1][row][1] + sred[2][row][1] + sred[3][row][1];
        mu[r] = S1 * (1.0f / 128.0f);
        float var = S2 * (1.0f / 128.0f) - mu[r] * mu[r];
        rs[r] = rsqrtf(var + 1e-5f);
    }

    #pragma unroll
    for (int nt = 0; nt < 4; nt++) {
        int c = wn * 32 + nt * 8 + 2 * t4;
        float2 gv = *(const float2*)&gma[c];
        float2 bv = *(const float2*)&bta[c];
        #pragma unroll
        for (int r = 0; r < 4; r++) {
            int gn = node0 + C + g + r * 8;
            if (gn >= NN) continue;
            float v0, v1;
            if (r == 0)      { v0 = acc0[nt][0]; v1 = acc0[nt][1]; }
            else if (r == 1) { v0 = acc0[nt][2]; v1 = acc0[nt][3]; }
            else if (r == 2) { v0 = acc1[nt][0]; v1 = acc1[nt][1]; }
            else             { v0 = acc1[nt][2]; v1 = acc1[nt][3]; }
            float2 res = *(const float2*)&xin[(size_t)gn * D + c];
            float o0 = gelu_exact((v0 - mu[r]) * rs[r] * gv.x + bv.x) + res.x;
            float o1 = gelu_exact((v1 - mu[r]) * rs[r] * gv.y + bv.y) + res.y;
            *(float2*)&xout[(size_t)gn * D + c] = make_float2(o0, o1);
        }
    }
}

// ---- gemm_pq: [p | q] = x2 @ [Wl3 | Wr3]  (tf32, same engine, K=128) ----

__global__ __launch_bounds__(256, 2) void gemm_pq(
    const float* __restrict__ Wl3, const float* __restrict__ Wr3)
{
    __shared__ uint2 Apk[64 * ASTR2];
    __shared__ uint2 Wpk[16 * WSTR2];

    const int tid = threadIdx.x;
    const int node0 = blockIdx.x * 64;
    const int warp = tid >> 5, lane = tid & 31;
    const int wm = warp & 1, wn = warp >> 1;
    const int g = lane >> 2, t4 = lane & 3;

    const int an0 = tid >> 3, an1 = (tid + 256) >> 3, af = tid & 7;
    const int koff = (af >> 1) * 8 + (af & 1);
    const float4 f4z = make_float4(0.f, 0.f, 0.f, 0.f);

    auto ldA = [&](int kc, float4& r0, float4& r1) {
        const float4* Asrc = (const float4*)g_x2;
        int kb = kc * 8;
        int gn0 = node0 + an0, gn1 = node0 + an1;
        r0 = (gn0 < NN) ? __ldg(&Asrc[(size_t)gn0 * 32 + kb + af]) : f4z;
        r1 = (gn1 < NN) ? __ldg(&Asrc[(size_t)gn1 * 32 + kb + af]) : f4z;
    };
    auto stA = [&](float4 r0, float4 r1) {
        uint32_t* Au = (uint32_t*)Apk;
        Au[an0 * 40 + koff + 0] = f2tf32(r0.x);
        Au[an0 * 40 + koff + 2] = f2tf32(r0.y);
        Au[an0 * 40 + koff + 4] = f2tf32(r0.z);
        Au[an0 * 40 + koff + 6] = f2tf32(r0.w);
        Au[an1 * 40 + koff + 0] = f2tf32(r1.x);
        Au[an1 * 40 + koff + 2] = f2tf32(r1.y);
        Au[an1 * 40 + koff + 4] = f2tf32(r1.z);
        Au[an1 * 40 + koff + 6] = f2tf32(r1.w);
    };
    // cols 0..63 from Wl3, 64..127 from Wr3 (both [128][64])
    auto ldW = [&](int kc, float4* w) {
        int kr0 = kc * 32;
        int p0 = 2 * warp, p1 = 2 * warp + 1;
        int k0 = (p0 >> 2) * 8 + (p0 & 3);
        int k1 = (p1 >> 2) * 8 + (p1 & 3);
        const float4* Wsrc = (lane < 16) ? (const float4*)Wl3 : (const float4*)Wr3;
        int cl = lane & 15;
        w[0] = __ldg(&Wsrc[(size_t)(kr0 + k0) * 16 + cl]);
        w[1] = __ldg(&Wsrc[(size_t)(kr0 + k0 + 4) * 16 + cl]);
        w[2] = __ldg(&Wsrc[(size_t)(kr0 + k1) * 16 + cl]);
        w[3] = __ldg(&Wsrc[(size_t)(kr0 + k1 + 4) * 16 + cl]);
    };
    auto stW = [&](const float4* w) {
        uint4* W4 = (uint4*)Wpk;
        #pragma unroll
        for (int q = 0; q < 2; q++) {
            int p = 2 * warp + q;
            float4 lo = w[2 * q], hi = w[2 * q + 1];
            W4[p * 66 + 2 * lane]     = make_uint4(f2tf32(lo.x), f2tf32(hi.x),
                                                   f2tf32(lo.y), f2tf32(hi.y));
            W4[p * 66 + 2 * lane + 1] = make_uint4(f2tf32(lo.z), f2tf32(hi.z),
                                                   f2tf32(lo.w), f2tf32(hi.w));
        }
    };

    float acc0[4][4], acc1[4][4];
    #pragma unroll
    for (int i = 0; i < 4; i++)
        #pragma unroll
        for (int j = 0; j < 4; j++) { acc0[i][j] = 0.f; acc1[i][j] = 0.f; }

    {
        float4 a0, a1, w0[4];
        ldA(0, a0, a1); ldW(0, w0);
        stA(a0, a1); stW(w0);
    }
    __syncthreads();

    const int C = wm * 32;
    for (int kc = 0; kc < 4; kc++) {
        float4 na0, na1, nw[4];
        if (kc < 3) { ldA(kc + 1, na0, na1); ldW(kc + 1, nw); }
        #pragma unroll
        for (int kk = 0; kk < 4; kk++) {
            int pbase = kk * 4 + t4;
            uint2 qa0 = Apk[(C + g)      * ASTR2 + pbase];
            uint2 qa1 = Apk[(C + g + 8)  * ASTR2 + pbase];
            uint2 qa2 = Apk[(C + g + 16) * ASTR2 + pbase];
            uint2 qa3 = Apk[(C + g + 24) * ASTR2 + pbase];
            #pragma unroll
            for (int nt = 0; nt < 4; nt++) {
                uint2 qb = Wpk[pbase * WSTR2 + wn * 32 + nt * 8 + g];
                mma_tf32(acc0[nt], qa0.x, qa1.x, qa0.y, qa1.y, qb.x, qb.y);
                mma_tf32(acc1[nt], qa2.x, qa3.x, qa2.y, qa3.y, qb.x, qb.y);
            }
        }
        __syncthreads();
        if (kc < 3) { stA(na0, na1); stW(nw); __syncthreads(); }
    }

    #pragma unroll
    for (int nt = 0; nt < 4; nt++) {
        int c = wn * 32 + nt * 8 + 2 * t4;
        float* dstbuf = (c < 64) ? g_p : g_q;
        int cc = c & 63;
        #pragma unroll
        for (int r = 0; r < 4; r++) {
            int gn = node0 + C + g + r * 8;
            if (gn >= NN) continue;
            float v0, v1;
            if (r == 0)      { v0 = acc0[nt][0]; v1 = acc0[nt][1]; }
            else if (r == 1) { v0 = acc0[nt][2]; v1 = acc0[nt][3]; }
            else if (r == 2) { v0 = acc1[nt][0]; v1 = acc1[nt][1]; }
            else             { v0 = acc1[nt][2]; v1 = acc1[nt][3]; }
            *(float2*)&dstbuf[(size_t)gn * DO + cc] = make_float2(v0, v1);
        }
    }
}

// ---- out_lite: gelu(q + agg64 + bl3) -> LN(64) -> @Wc + bcls ----

__global__ __launch_bounds__(256) void out_lite(
    const float* __restrict__ bl3,
    const float* __restrict__ gc, const float* __restrict__ bc,
    const float* __restrict__ Wc, const float* __restrict__ bcls,
    float* __restrict__ out)
{
    __shared__ float Wcs[DO * NC];   // 10240 B
    __shared__ float bcs[NC];
    __shared__ float Vs[64 * 66];    // 16896 B
    const int tid = threadIdx.x;
    const int node0 = blockIdx.x * 64;

    for (int i = tid; i < DO * NC; i += 256)
        Wcs[i] = __ldg(&Wc[i]);
    if (tid < NC) bcs[tid] = __ldg(&bcls[tid]);

    const int warp = tid >> 5, lane = tid & 31;
    const int nbase = warp * 8;
    float2 b3v = __ldg(&((const float2*)bl3)[lane]);
    float2 gcv = __ldg(&((const float2*)gc)[lane]);
    float2 bcv = __ldg(&((const float2*)bc)[lane]);

    #pragma unroll
    for (int n = 0; n < 8; n++) {
        int gn = node0 + nbase + n;
        float2 q  = (gn < NN) ? __ldg(&((const float2*)g_q)[(size_t)gn * 32 + lane])
                              : make_float2(0.f, 0.f);
        float2 ag = (gn < NN) ? __ldg(&((const float2*)g_agg64)[(size_t)gn * 32 + lane])
                              : make_float2(0.f, 0.f);
        float u0 = gelu_exact(q.x + ag.x + b3v.x);
        float u1 = gelu_exact(q.y + ag.y + b3v.y);
        float s1 = u0 + u1, s2 = u0 * u0 + u1 * u1;
        #pragma unroll
        for (int off = 16; off; off >>= 1) {
            s1 += __shfl_xor_sync(0xffffffffu, s1, off);
            s2 += __shfl_xor_sync(0xffffffffu, s2, off);
        }
        float mu = s1 * (1.0f / 64.0f);
        float var = s2 * (1.0f / 64.0f) - mu * mu;
        float rstd = rsqrtf(var + 1e-5f);
        Vs[(nbase + n) * 66 + 2 * lane]     = (u0 - mu) * rstd * gcv.x + bcv.x;
        Vs[(nbase + n) * 66 + 2 * lane + 1] = (u1 - mu) * rstd * gcv.y + bcv.y;
    }
    __syncthreads();

    int n = tid >> 2, cg = (tid & 3) * 10;
    float o[10];
    #pragma unroll
    for (int j = 0; j < 10; j++) o[j] = bcs[cg + j];
    #pragma unroll 8
    for (int k = 0; k < DO; k++) {
        float vv = Vs[n * 66 + k];
        #pragma unroll
        for (int j = 0; j < 10; j++)
            o[j] += vv * Wcs[k * NC + cg + j];
    }
    int gn = node0 + n;
    if (gn < NN) {
        #pragma unroll
        for (int j = 0; j < 10; j++)
            out[(size_t)gn * NC + cg + j] = o[j];
    }
}

// ---------------- launcher ----------------

extern "C" void kernel_launch(void* const* d_in, const int* in_sizes, int n_in,
                              void* d_out, int out_size)
{
    const float* x    = (const float*)d_in[0];
    const int*   ei   = (const int*)d_in[1];
    const float* Wl1  = (const float*)d_in[2];
    const float* bl1  = (const float*)d_in[3];
    const float* Wr1  = (const float*)d_in[4];
    const float* g1   = (const float*)d_in[5];
    const float* b1   = (const float*)d_in[6];
    const float* Wl2  = (const float*)d_in[7];
    const float* bl2  = (const float*)d_in[8];
    const float* Wr2  = (const float*)d_in[9];
    const float* g2   = (const float*)d_in[10];
    const float* b2   = (const float*)d_in[11];
    const float* Wl3  = (const float*)d_in[12];
    const float* bl3  = (const float*)d_in[13];
    const float* Wr3  = (const float*)d_in[14];
    const float* gc   = (const float*)d_in[15];
    const float* bc   = (const float*)d_in[16];
    const float* Wc   = (const float*)d_in[17];
    const float* bcls = (const float*)d_in[18];
    const int* src = ei;
    const int* dst = ei + NE;
    float* out = (float*)d_out;

    void *p_x1 = nullptr, *p_x2 = nullptr;
    cudaGetSymbolAddress(&p_x1, g_x1);
    cudaGetSymbolAddress(&p_x2, g_x2);

    const int nbn = (NN + 63) / 64;
    const int nbe = (NE + 255) / 256;
    const int nbw = ((NN * 32) + 255) / 256;   // one warp per node

    // CSR build
    zero_deg_cur<<<(NN + 255) / 256, 256>>>();
    count_deg<<<nbe, 256>>>(dst);
    scan_local<<<SCAN_B, SCAN_T>>>();
    scan_bsum<<<1, 128>>>();
    scan_add<<<(NN + 255) / 256, 256>>>();
    fill_edges<<<nbe, 256>>>(src, dst);

    // Layer 1
    gather128<<<nbw, 256>>>(x);
    sage_tc2<<<nbn, 256>>>(x, Wl1, bl1, Wr1, g1, b1, (float*)p_x1);

    // Layer 2
    gather128<<<nbw, 256>>>((const float*)p_x1);
    sage_tc2<<<nbn, 256>>>((const float*)p_x1, Wl2, bl2, Wr2, g2, b2, (float*)p_x2);

    // Layer 3: [p|q] = x2 @ [Wl3|Wr3], gather p, then light epilogue + classifier
    gemm_pq<<<nbn, 256>>>(Wl3, Wr3);
    gather64<<<nbw, 256>>>();
    out_lite<<<nbn, 256>>>(bl3, gc, bc, Wc, bcls, out);
}